// round 5
// baseline (speedup 1.0000x reference)
#include <cuda_runtime.h>
#include <math.h>
#include <stdint.h>

#define BATCH 2
#define SEQL  2048
#define DMODEL 1024
#define NHEADS 16
#define DK    64
#define DFF   4096
#define TOKENS (BATCH*SEQL)   // 4096

// ---------------- scratch (device globals: allocation-guard safe) -----------
__device__ float g_qkv[TOKENS*3*DMODEL];
__device__ float g_attnv[TOKENS*DMODEL];
__device__ float g_tmp[TOKENS*DMODEL];
__device__ float g_x1[TOKENS*DMODEL];
__device__ float g_ff[TOKENS*DFF];
__device__ float g_tmp2[TOKENS*DMODEL];
__device__ float g_bias3[3*DMODEL];

// ---------------- helpers ----------------------------------------------------
__device__ __forceinline__ void mma_tf32(float c[4],
    uint32_t a0, uint32_t a1, uint32_t a2, uint32_t a3,
    uint32_t b0, uint32_t b1)
{
    asm volatile(
        "mma.sync.aligned.m16n8k8.row.col.f32.tf32.tf32.f32 "
        "{%0,%1,%2,%3}, {%4,%5,%6,%7}, {%8,%9}, {%0,%1,%2,%3};"
        : "+f"(c[0]), "+f"(c[1]), "+f"(c[2]), "+f"(c[3])
        : "r"(a0), "r"(a1), "r"(a2), "r"(a3), "r"(b0), "r"(b1));
}

__device__ __forceinline__ void cp16(uint32_t dst, const void* src) {
    asm volatile("cp.async.cg.shared.global [%0], [%1], 16;" :: "r"(dst), "l"(src));
}
__device__ __forceinline__ void cp_commit() { asm volatile("cp.async.commit_group;"); }
__device__ __forceinline__ void cp_wait0()  { asm volatile("cp.async.wait_group 0;"); }

// ---------------- TF32 GEMM, 256x128 tile, BK=32, cp.async double buffer ----
// 256 thr (8 warps), warp tile 64x64 (4x8 m16n8k8 tiles). Raw fp32 bits fed to
// tf32 MMA (HW truncation). Supports fused-QKV via 3 B pointers (col select).
#define A_PAD 36
#define B_PAD 136
#define ASTG (256*A_PAD)
#define BSTG (32*B_PAD)
#define GEMM_SMEM_BYTES (2*(ASTG+BSTG)*4)

__global__ __launch_bounds__(256, 1) void tgemm_bias(
    const float* __restrict__ A,
    const float* __restrict__ B0, const float* __restrict__ B1,
    const float* __restrict__ B2,
    const float* __restrict__ bias, float* __restrict__ C,
    int M, int N, int K, int ldb, int gelu)
{
    extern __shared__ uint32_t sg[];
    uint32_t* As = sg;            // [2][256][A_PAD]
    uint32_t* Bs = sg + 2*ASTG;   // [2][32][B_PAD]
    const uint32_t asB = (uint32_t)__cvta_generic_to_shared(As);
    const uint32_t bsB = (uint32_t)__cvta_generic_to_shared(Bs);

    const int tid  = threadIdx.x;
    const int lane = tid & 31;
    const int warp = tid >> 5;
    const int r4 = lane >> 2, q4 = lane & 3;
    const int wm = (warp & 3) * 64;
    const int wn = (warp >> 2) * 64;
    const int rowBase = blockIdx.y * 256;
    const int colBase = blockIdx.x * 128;

    // fused-QKV column select (each 128-col block lies in one source matrix)
    const float* Bw = B0;
    int cb = colBase;
    if (B1 && colBase >= ldb) { Bw = B1; cb = colBase - ldb; }
    if (B2 && colBase >= 2 * ldb) { Bw = B2; cb = colBase - 2 * ldb; }

    float acc[4][8][4];
    #pragma unroll
    for (int i = 0; i < 4; i++)
        #pragma unroll
        for (int j = 0; j < 8; j++)
            #pragma unroll
            for (int r = 0; r < 4; r++) acc[i][j][r] = 0.f;

    const int NC = K / 32;

    // issue stage 0
    {
        #pragma unroll
        for (int i = 0; i < 8; i++) {
            int f = tid + i * 256;
            int r = f >> 3, c4 = (f & 7) * 4;
            cp16(asB + ((r * A_PAD + c4) << 2),
                 A + (size_t)(rowBase + r) * K + c4);
        }
        #pragma unroll
        for (int i = 0; i < 4; i++) {
            int f = tid + i * 256;
            int r = f >> 5, c4 = (f & 31) * 4;
            cp16(bsB + ((r * B_PAD + c4) << 2),
                 Bw + (size_t)r * ldb + cb + c4);
        }
        cp_commit();
    }

    for (int ic = 0; ic < NC; ic++) {
        cp_wait0();
        __syncthreads();

        if (ic + 1 < NC) {
            int st = (ic + 1) & 1;
            int k0 = (ic + 1) * 32;
            #pragma unroll
            for (int i = 0; i < 8; i++) {
                int f = tid + i * 256;
                int r = f >> 3, c4 = (f & 7) * 4;
                cp16(asB + ((st * ASTG + r * A_PAD + c4) << 2),
                     A + (size_t)(rowBase + r) * K + k0 + c4);
            }
            #pragma unroll
            for (int i = 0; i < 4; i++) {
                int f = tid + i * 256;
                int r = f >> 5, c4 = (f & 31) * 4;
                cp16(bsB + ((st * BSTG + r * B_PAD + c4) << 2),
                     Bw + (size_t)(k0 + r) * ldb + cb + c4);
            }
            cp_commit();
        }

        const uint32_t* Asl = As + (ic & 1) * ASTG;
        const uint32_t* Bsl = Bs + (ic & 1) * BSTG;
        #pragma unroll
        for (int kk = 0; kk < 4; kk++) {
            uint32_t af[4][4], bf[8][2];
            #pragma unroll
            for (int mf = 0; mf < 4; mf++) {
                int r = wm + mf * 16 + r4;
                int c = kk * 8 + q4;
                af[mf][0] = Asl[r * A_PAD + c];
                af[mf][1] = Asl[(r + 8) * A_PAD + c];
                af[mf][2] = Asl[r * A_PAD + c + 4];
                af[mf][3] = Asl[(r + 8) * A_PAD + c + 4];
            }
            #pragma unroll
            for (int nf = 0; nf < 8; nf++) {
                int cc = wn + nf * 8 + r4;
                int rr = kk * 8 + q4;
                bf[nf][0] = Bsl[rr * B_PAD + cc];
                bf[nf][1] = Bsl[(rr + 4) * B_PAD + cc];
            }
            #pragma unroll
            for (int mf = 0; mf < 4; mf++)
                #pragma unroll
                for (int nf = 0; nf < 8; nf++)
                    mma_tf32(acc[mf][nf], af[mf][0], af[mf][1], af[mf][2], af[mf][3],
                             bf[nf][0], bf[nf][1]);
        }
    }

    #pragma unroll
    for (int mf = 0; mf < 4; mf++) {
        #pragma unroll
        for (int nf = 0; nf < 8; nf++) {
            int row = rowBase + wm + mf * 16 + r4;
            int col = colBase + wn + nf * 8 + 2 * q4;
            float v0 = acc[mf][nf][0] + bias[col];
            float v1 = acc[mf][nf][1] + bias[col + 1];
            float v2 = acc[mf][nf][2] + bias[col];
            float v3 = acc[mf][nf][3] + bias[col + 1];
            if (gelu) {
                v0 = 0.5f * v0 * (1.f + erff(v0 * 0.70710678118654752f));
                v1 = 0.5f * v1 * (1.f + erff(v1 * 0.70710678118654752f));
                v2 = 0.5f * v2 * (1.f + erff(v2 * 0.70710678118654752f));
                v3 = 0.5f * v3 * (1.f + erff(v3 * 0.70710678118654752f));
            }
            *(float2*)(C + (size_t)row * N + col)       = make_float2(v0, v1);
            *(float2*)(C + (size_t)(row + 8) * N + col) = make_float2(v2, v3);
        }
    }
}

// ---------------- tensor-core flash attention, cp.async double-buffered -----
#define KS_PAD 68
#define VS_PAD 72
#define PS_PAD 132
#define KSTG (128*KS_PAD)
#define VSTG (128*VS_PAD)
#define ATT_SMEM_BYTES ((2*KSTG + 2*VSTG + 128*PS_PAD) * 4)
#define LDQKV (3*DMODEL)

__global__ __launch_bounds__(256, 1) void attn_tc(
    const float* __restrict__ qkv, float* __restrict__ o_out)
{
    extern __shared__ uint32_t sm[];
    uint32_t* Ks = sm;                      // [2][128][KS_PAD]
    uint32_t* Vs = sm + 2 * KSTG;           // [2][128][VS_PAD]
    uint32_t* Ps = sm + 2 * (KSTG + VSTG);  // [128][PS_PAD]
    const uint32_t ksB = (uint32_t)__cvta_generic_to_shared(Ks);
    const uint32_t vsB = (uint32_t)__cvta_generic_to_shared(Vs);

    const int tid  = threadIdx.x;
    const int lane = tid & 31;
    const int warp = tid >> 5;
    const int r4 = lane >> 2, q4 = lane & 3;
    const int bh = blockIdx.y;
    const int b  = bh >> 4;
    const int hh = bh & 15;
    const int qbase = blockIdx.x * 128;
    const int wrow  = warp * 16;

    const float* qp = qkv + ((size_t)(b * SEQL + qbase + wrow)) * LDQKV + hh * DK;
    const float* kbase = qkv + (size_t)b * SEQL * LDQKV + DMODEL + hh * DK;
    const float* vbase = qkv + (size_t)b * SEQL * LDQKV + 2 * DMODEL + hh * DK;

    // Q fragments: raw fp32 bits (HW tf32 truncation); scale applied to S later
    uint32_t qf[8][4];
    #pragma unroll
    for (int kk = 0; kk < 8; kk++) {
        qf[kk][0] = __float_as_uint(qp[(size_t)r4       * LDQKV + kk * 8 + q4    ]);
        qf[kk][1] = __float_as_uint(qp[(size_t)(r4 + 8) * LDQKV + kk * 8 + q4    ]);
        qf[kk][2] = __float_as_uint(qp[(size_t)r4       * LDQKV + kk * 8 + q4 + 4]);
        qf[kk][3] = __float_as_uint(qp[(size_t)(r4 + 8) * LDQKV + kk * 8 + q4 + 4]);
    }

    float oacc[8][4];
    #pragma unroll
    for (int nf = 0; nf < 8; nf++)
        #pragma unroll
        for (int r = 0; r < 4; r++) oacc[nf][r] = 0.f;

    float m0 = -1e30f, m8 = -1e30f, l0 = 0.f, l8 = 0.f;

    // issue tile 0
    {
        #pragma unroll
        for (int i = 0; i < 8; i++) {
            int f = tid + i * 256;
            int key = f >> 4, d4 = (f & 15) * 4;
            cp16(ksB + ((key * KS_PAD + d4) << 2), kbase + (size_t)key * LDQKV + d4);
            cp16(vsB + ((key * VS_PAD + d4) << 2), vbase + (size_t)key * LDQKV + d4);
        }
        cp_commit();
    }

    const int NT = SEQL / 128;
    for (int t = 0; t < NT; t++) {
        cp_wait0();
        __syncthreads();

        if (t + 1 < NT) {
            int st = (t + 1) & 1;
            int kt = (t + 1) * 128;
            #pragma unroll
            for (int i = 0; i < 8; i++) {
                int f = tid + i * 256;
                int key = f >> 4, d4 = (f & 15) * 4;
                cp16(ksB + ((st * KSTG + key * KS_PAD + d4) << 2),
                     kbase + (size_t)(kt + key) * LDQKV + d4);
                cp16(vsB + ((st * VSTG + key * VS_PAD + d4) << 2),
                     vbase + (size_t)(kt + key) * LDQKV + d4);
            }
            cp_commit();
        }

        const uint32_t* Ksl = Ks + (t & 1) * KSTG;
        const uint32_t* Vsl = Vs + (t & 1) * VSTG;

        // S = Q @ K^T (16 x 128 per warp)
        float sacc[16][4];
        #pragma unroll
        for (int nf = 0; nf < 16; nf++)
            #pragma unroll
            for (int r = 0; r < 4; r++) sacc[nf][r] = 0.f;

        #pragma unroll
        for (int kk = 0; kk < 8; kk++) {
            #pragma unroll
            for (int nf = 0; nf < 16; nf++) {
                uint32_t b0 = Ksl[(nf * 8 + r4) * KS_PAD + kk * 8 + q4];
                uint32_t b1 = Ksl[(nf * 8 + r4) * KS_PAD + kk * 8 + q4 + 4];
                mma_tf32(sacc[nf], qf[kk][0], qf[kk][1], qf[kk][2], qf[kk][3], b0, b1);
            }
        }
        #pragma unroll
        for (int nf = 0; nf < 16; nf++) {
            sacc[nf][0] *= 0.125f; sacc[nf][1] *= 0.125f;
            sacc[nf][2] *= 0.125f; sacc[nf][3] *= 0.125f;
        }

        // online softmax
        float mx0 = -1e30f, mx8 = -1e30f;
        #pragma unroll
        for (int nf = 0; nf < 16; nf++) {
            mx0 = fmaxf(mx0, fmaxf(sacc[nf][0], sacc[nf][1]));
            mx8 = fmaxf(mx8, fmaxf(sacc[nf][2], sacc[nf][3]));
        }
        mx0 = fmaxf(mx0, __shfl_xor_sync(0xffffffffu, mx0, 1));
        mx0 = fmaxf(mx0, __shfl_xor_sync(0xffffffffu, mx0, 2));
        mx8 = fmaxf(mx8, __shfl_xor_sync(0xffffffffu, mx8, 1));
        mx8 = fmaxf(mx8, __shfl_xor_sync(0xffffffffu, mx8, 2));

        float mn0 = fmaxf(m0, mx0), mn8 = fmaxf(m8, mx8);
        float sc0 = __expf(m0 - mn0), sc8 = __expf(m8 - mn8);
        m0 = mn0; m8 = mn8;
        l0 *= sc0; l8 *= sc8;
        #pragma unroll
        for (int nf = 0; nf < 8; nf++) {
            oacc[nf][0] *= sc0; oacc[nf][1] *= sc0;
            oacc[nf][2] *= sc8; oacc[nf][3] *= sc8;
        }

        float rs0 = 0.f, rs8 = 0.f;
        uint32_t* pw0 = Ps + (wrow + r4) * PS_PAD;
        uint32_t* pw8 = Ps + (wrow + r4 + 8) * PS_PAD;
        #pragma unroll
        for (int nf = 0; nf < 16; nf++) {
            float p0 = __expf(sacc[nf][0] - m0);
            float p1 = __expf(sacc[nf][1] - m0);
            float p2 = __expf(sacc[nf][2] - m8);
            float p3 = __expf(sacc[nf][3] - m8);
            rs0 += p0 + p1; rs8 += p2 + p3;
            int col = nf * 8 + 2 * q4;
            pw0[col] = __float_as_uint(p0); pw0[col + 1] = __float_as_uint(p1);
            pw8[col] = __float_as_uint(p2); pw8[col + 1] = __float_as_uint(p3);
        }
        rs0 += __shfl_xor_sync(0xffffffffu, rs0, 1);
        rs0 += __shfl_xor_sync(0xffffffffu, rs0, 2);
        rs8 += __shfl_xor_sync(0xffffffffu, rs8, 1);
        rs8 += __shfl_xor_sync(0xffffffffu, rs8, 2);
        l0 += rs0; l8 += rs8;
        __syncwarp();   // P rows are warp-private

        // O += P @ V
        #pragma unroll
        for (int kk = 0; kk < 16; kk++) {
            uint32_t a0 = Ps[(wrow + r4)     * PS_PAD + kk * 8 + q4];
            uint32_t a1 = Ps[(wrow + r4 + 8) * PS_PAD + kk * 8 + q4];
            uint32_t a2 = Ps[(wrow + r4)     * PS_PAD + kk * 8 + q4 + 4];
            uint32_t a3 = Ps[(wrow + r4 + 8) * PS_PAD + kk * 8 + q4 + 4];
            #pragma unroll
            for (int nf = 0; nf < 8; nf++) {
                uint32_t b0 = Vsl[(kk * 8 + q4)     * VS_PAD + nf * 8 + r4];
                uint32_t b1 = Vsl[(kk * 8 + q4 + 4) * VS_PAD + nf * 8 + r4];
                mma_tf32(oacc[nf], a0, a1, a2, a3, b0, b1);
            }
        }
    }

    // epilogue, reference's no-transpose reshape
    const float inv0 = 1.f / l0, inv8 = 1.f / l8;
    const int lg0 = qbase + wrow + r4;
    const int lg8 = lg0 + 8;
    #pragma unroll
    for (int nf = 0; nf < 8; nf++) {
        int d = nf * 8 + 2 * q4;
        int row0 = hh * 128 + (lg0 >> 4), col0 = (lg0 & 15) * 64 + d;
        int row8 = hh * 128 + (lg8 >> 4), col8 = (lg8 & 15) * 64 + d;
        *(float2*)(o_out + ((size_t)(b * SEQL + row0)) * DMODEL + col0) =
            make_float2(oacc[nf][0] * inv0, oacc[nf][1] * inv0);
        *(float2*)(o_out + ((size_t)(b * SEQL + row8)) * DMODEL + col8) =
            make_float2(oacc[nf][2] * inv8, oacc[nf][3] * inv8);
    }
}

// ---------------- residual add + LayerNorm ----------------------------------
__global__ __launch_bounds__(256) void add_ln_kernel(
    const float* __restrict__ a, const float* __restrict__ b,
    const float* __restrict__ g, const float* __restrict__ beta,
    float* __restrict__ out)
{
    const int row = blockIdx.x;
    const int tid = threadIdx.x;
    const float* ar = a + (size_t)row * DMODEL;
    const float* br = b + (size_t)row * DMODEL;

    float x[4];
    float sum = 0.f, sq = 0.f;
    #pragma unroll
    for (int i = 0; i < 4; i++) {
        int c = tid + i * 256;
        x[i] = ar[c] + br[c];
        sum += x[i];
        sq  += x[i] * x[i];
    }
    #pragma unroll
    for (int off = 16; off; off >>= 1) {
        sum += __shfl_xor_sync(0xffffffffu, sum, off);
        sq  += __shfl_xor_sync(0xffffffffu, sq, off);
    }
    __shared__ float ssum[8], ssq[8];
    const int wid = tid >> 5;
    if ((tid & 31) == 0) { ssum[wid] = sum; ssq[wid] = sq; }
    __syncthreads();
    sum = 0.f; sq = 0.f;
    #pragma unroll
    for (int w = 0; w < 8; w++) { sum += ssum[w]; sq += ssq[w]; }

    const float mean = sum * (1.f / DMODEL);
    const float var  = sq * (1.f / DMODEL) - mean * mean;
    const float rstd = rsqrtf(var + 1e-5f);

    float* orow = out + (size_t)row * DMODEL;
    #pragma unroll
    for (int i = 0; i < 4; i++) {
        int c = tid + i * 256;
        orow[c] = (x[i] - mean) * rstd * g[c] + beta[c];
    }
}

// ---------------- bias concat ------------------------------------------------
__global__ void concat_bias(const float* a, const float* b, const float* c,
                            float* o)
{
    int i = blockIdx.x * 256 + threadIdx.x;
    if (i < DMODEL) {
        o[i] = a[i];
        o[i + DMODEL] = b[i];
        o[i + 2 * DMODEL] = c[i];
    }
}

// ---------------- launch ----------------------------------------------------
extern "C" void kernel_launch(void* const* d_in, const int* in_sizes, int n_in,
                              void* d_out, int out_size)
{
    const float* x    = (const float*)d_in[0];
    const float* Wq   = (const float*)d_in[1];
    const float* bq   = (const float*)d_in[2];
    const float* Wk   = (const float*)d_in[3];
    const float* bk   = (const float*)d_in[4];
    const float* Wv   = (const float*)d_in[5];
    const float* bv   = (const float*)d_in[6];
    const float* Wo   = (const float*)d_in[7];
    const float* bo   = (const float*)d_in[8];
    const float* W1   = (const float*)d_in[9];
    const float* b1   = (const float*)d_in[10];
    const float* W2   = (const float*)d_in[11];
    const float* b2   = (const float*)d_in[12];
    const float* g1   = (const float*)d_in[13];
    const float* bt1  = (const float*)d_in[14];
    const float* g2   = (const float*)d_in[15];
    const float* bt2  = (const float*)d_in[16];
    float* out = (float*)d_out;

    float *qkv, *attnv, *tmp, *x1, *ff, *tmp2, *bias3;
    cudaGetSymbolAddress((void**)&qkv,   g_qkv);
    cudaGetSymbolAddress((void**)&attnv, g_attnv);
    cudaGetSymbolAddress((void**)&tmp,   g_tmp);
    cudaGetSymbolAddress((void**)&x1,    g_x1);
    cudaGetSymbolAddress((void**)&ff,    g_ff);
    cudaGetSymbolAddress((void**)&tmp2,  g_tmp2);
    cudaGetSymbolAddress((void**)&bias3, g_bias3);

    cudaFuncSetAttribute(tgemm_bias, cudaFuncAttributeMaxDynamicSharedMemorySize,
                         GEMM_SMEM_BYTES);
    cudaFuncSetAttribute(attn_tc, cudaFuncAttributeMaxDynamicSharedMemorySize,
                         ATT_SMEM_BYTES);

    concat_bias<<<4, 256>>>(bq, bk, bv, bias3);

    // fused QKV projection: [4096 x 1024] @ [1024 x 3072]
    dim3 gQKV(3 * DMODEL / 128, TOKENS / 256);  // (24, 16)
    tgemm_bias<<<gQKV, 256, GEMM_SMEM_BYTES>>>(
        x, Wq, Wk, Wv, bias3, qkv, TOKENS, 3 * DMODEL, DMODEL, DMODEL, 0);

    // tensor-core flash attention over the fused buffer
    dim3 gA(SEQL / 128, BATCH * NHEADS);        // (16, 32)
    attn_tc<<<gA, 256, ATT_SMEM_BYTES>>>(qkv, attnv);

    // output projection + residual LN
    dim3 gD(DMODEL / 128, TOKENS / 256);        // (8, 16)
    tgemm_bias<<<gD, 256, GEMM_SMEM_BYTES>>>(
        attnv, Wo, nullptr, nullptr, bo, tmp, TOKENS, DMODEL, DMODEL, DMODEL, 0);
    add_ln_kernel<<<TOKENS, 256>>>(tmp, x, g1, bt1, x1);

    // FFN
    dim3 gF(DFF / 128, TOKENS / 256);           // (32, 16)
    tgemm_bias<<<gF, 256, GEMM_SMEM_BYTES>>>(
        x1, W1, nullptr, nullptr, b1, ff, TOKENS, DFF, DMODEL, DFF, 1);
    tgemm_bias<<<gD, 256, GEMM_SMEM_BYTES>>>(
        ff, W2, nullptr, nullptr, b2, tmp2, TOKENS, DMODEL, DFF, DMODEL, 0);
    add_ln_kernel<<<TOKENS, 256>>>(tmp2, x1, g2, bt2, out);
}

// round 9
// speedup vs baseline: 1.0222x; 1.0222x over previous
#include <cuda_runtime.h>
#include <math.h>
#include <stdint.h>

#define BATCH 2
#define SEQL  2048
#define DMODEL 1024
#define NHEADS 16
#define DK    64
#define DFF   4096
#define TOKENS (BATCH*SEQL)   // 4096

// ---------------- scratch (device globals: allocation-guard safe) -----------
__device__ float g_qkv[TOKENS*3*DMODEL];
__device__ float g_attnv[TOKENS*DMODEL];
__device__ float g_tmp[TOKENS*DMODEL];
__device__ float g_x1[TOKENS*DMODEL];
__device__ float g_ff[TOKENS*DFF];
__device__ float g_tmp2[TOKENS*DMODEL];
__device__ float g_bias3[3*DMODEL];

// ---------------- helpers ----------------------------------------------------
__device__ __forceinline__ void mma_tf32(float c[4],
    uint32_t a0, uint32_t a1, uint32_t a2, uint32_t a3,
    uint32_t b0, uint32_t b1)
{
    asm volatile(
        "mma.sync.aligned.m16n8k8.row.col.f32.tf32.tf32.f32 "
        "{%0,%1,%2,%3}, {%4,%5,%6,%7}, {%8,%9}, {%0,%1,%2,%3};"
        : "+f"(c[0]), "+f"(c[1]), "+f"(c[2]), "+f"(c[3])
        : "r"(a0), "r"(a1), "r"(a2), "r"(a3), "r"(b0), "r"(b1));
}

__device__ __forceinline__ void cp16(uint32_t dst, const void* src) {
    asm volatile("cp.async.cg.shared.global [%0], [%1], 16;" :: "r"(dst), "l"(src));
}
__device__ __forceinline__ void cp_commit() { asm volatile("cp.async.commit_group;"); }
__device__ __forceinline__ void cp_wait0()  { asm volatile("cp.async.wait_group 0;"); }

// ---------------- TF32 GEMM, 128x128 tile, BK=32, 2 CTAs/SM -----------------
// 256 thr (8 warps), warp tile 32x64 (2x8 m16n8k8). Raw fp32 bits -> tf32 HW
// truncation. cp.async double buffer. occupancy 2 for latency hiding.
#define A_PAD 36
#define B_PAD 136
#define ASTG (128*A_PAD)
#define BSTG (32*B_PAD)
#define GEMM_SMEM_BYTES (2*(ASTG+BSTG)*4)   // ~70 KB

__global__ __launch_bounds__(256, 2) void tgemm_bias(
    const float* __restrict__ A,
    const float* __restrict__ B0, const float* __restrict__ B1,
    const float* __restrict__ B2,
    const float* __restrict__ bias, float* __restrict__ C,
    int M, int N, int K, int ldb, int gelu)
{
    extern __shared__ uint32_t sg[];
    uint32_t* As = sg;            // [2][128][A_PAD]
    uint32_t* Bs = sg + 2*ASTG;   // [2][32][B_PAD]
    const uint32_t asB = (uint32_t)__cvta_generic_to_shared(As);
    const uint32_t bsB = (uint32_t)__cvta_generic_to_shared(Bs);

    const int tid  = threadIdx.x;
    const int lane = tid & 31;
    const int warp = tid >> 5;
    const int r4 = lane >> 2, q4 = lane & 3;
    const int wm = (warp & 3) * 32;     // 4 warps in M
    const int wn = (warp >> 2) * 64;    // 2 warps in N
    const int rowBase = blockIdx.y * 128;
    const int colBase = blockIdx.x * 128;

    // fused-QKV column select (each 128-col block lies in one source matrix)
    const float* Bw = B0;
    int cb = colBase;
    if (B1 && colBase >= ldb) { Bw = B1; cb = colBase - ldb; }
    if (B2 && colBase >= 2 * ldb) { Bw = B2; cb = colBase - 2 * ldb; }

    float acc[2][8][4];
    #pragma unroll
    for (int i = 0; i < 2; i++)
        #pragma unroll
        for (int j = 0; j < 8; j++)
            #pragma unroll
            for (int r = 0; r < 4; r++) acc[i][j][r] = 0.f;

    const int NC = K / 32;

    // stage 0: A tile 128x32 = 1024 float4? no: 128*32/4 = 1024 float4 / 256 thr = 4 each
    {
        #pragma unroll
        for (int i = 0; i < 4; i++) {
            int f = tid + i * 256;
            int r = f >> 3, c4 = (f & 7) * 4;
            cp16(asB + ((r * A_PAD + c4) << 2), A + (size_t)(rowBase + r) * K + c4);
        }
        #pragma unroll
        for (int i = 0; i < 4; i++) {
            int f = tid + i * 256;
            int r = f >> 5, c4 = (f & 31) * 4;
            cp16(bsB + ((r * B_PAD + c4) << 2), Bw + (size_t)r * ldb + cb + c4);
        }
        cp_commit();
    }

    for (int ic = 0; ic < NC; ic++) {
        cp_wait0();
        __syncthreads();

        if (ic + 1 < NC) {
            int st = (ic + 1) & 1;
            int k0 = (ic + 1) * 32;
            #pragma unroll
            for (int i = 0; i < 4; i++) {
                int f = tid + i * 256;
                int r = f >> 3, c4 = (f & 7) * 4;
                cp16(asB + ((st * ASTG + r * A_PAD + c4) << 2),
                     A + (size_t)(rowBase + r) * K + k0 + c4);
            }
            #pragma unroll
            for (int i = 0; i < 4; i++) {
                int f = tid + i * 256;
                int r = f >> 5, c4 = (f & 31) * 4;
                cp16(bsB + ((st * BSTG + r * B_PAD + c4) << 2),
                     Bw + (size_t)(k0 + r) * ldb + cb + c4);
            }
            cp_commit();
        }

        const uint32_t* Asl = As + (ic & 1) * ASTG;
        const uint32_t* Bsl = Bs + (ic & 1) * BSTG;
        #pragma unroll
        for (int kk = 0; kk < 4; kk++) {
            uint32_t af[2][4], bf[8][2];
            #pragma unroll
            for (int mf = 0; mf < 2; mf++) {
                int r = wm + mf * 16 + r4;
                int c = kk * 8 + q4;
                af[mf][0] = Asl[r * A_PAD + c];
                af[mf][1] = Asl[(r + 8) * A_PAD + c];
                af[mf][2] = Asl[r * A_PAD + c + 4];
                af[mf][3] = Asl[(r + 8) * A_PAD + c + 4];
            }
            #pragma unroll
            for (int nf = 0; nf < 8; nf++) {
                int cc = wn + nf * 8 + r4;
                int rr = kk * 8 + q4;
                bf[nf][0] = Bsl[rr * B_PAD + cc];
                bf[nf][1] = Bsl[(rr + 4) * B_PAD + cc];
            }
            #pragma unroll
            for (int mf = 0; mf < 2; mf++)
                #pragma unroll
                for (int nf = 0; nf < 8; nf++)
                    mma_tf32(acc[mf][nf], af[mf][0], af[mf][1], af[mf][2], af[mf][3],
                             bf[nf][0], bf[nf][1]);
        }
        __syncthreads();
    }

    #pragma unroll
    for (int mf = 0; mf < 2; mf++) {
        #pragma unroll
        for (int nf = 0; nf < 8; nf++) {
            int row = rowBase + wm + mf * 16 + r4;
            int col = colBase + wn + nf * 8 + 2 * q4;
            float v0 = acc[mf][nf][0] + bias[col];
            float v1 = acc[mf][nf][1] + bias[col + 1];
            float v2 = acc[mf][nf][2] + bias[col];
            float v3 = acc[mf][nf][3] + bias[col + 1];
            if (gelu) {
                v0 = 0.5f * v0 * (1.f + erff(v0 * 0.70710678118654752f));
                v1 = 0.5f * v1 * (1.f + erff(v1 * 0.70710678118654752f));
                v2 = 0.5f * v2 * (1.f + erff(v2 * 0.70710678118654752f));
                v3 = 0.5f * v3 * (1.f + erff(v3 * 0.70710678118654752f));
            }
            *(float2*)(C + (size_t)row * N + col)       = make_float2(v0, v1);
            *(float2*)(C + (size_t)(row + 8) * N + col) = make_float2(v2, v3);
        }
    }
}

// ---------------- tensor-core flash attention, cp.async double-buffered -----
#define KS_PAD 68
#define VS_PAD 72
#define PS_PAD 132
#define KSTG (128*KS_PAD)
#define VSTG (128*VS_PAD)
#define ATT_SMEM_BYTES ((2*KSTG + 2*VSTG + 128*PS_PAD) * 4)
#define LDQKV (3*DMODEL)

__global__ __launch_bounds__(256, 1) void attn_tc(
    const float* __restrict__ qkv, float* __restrict__ o_out)
{
    extern __shared__ uint32_t sm[];
    uint32_t* Ks = sm;                      // [2][128][KS_PAD]
    uint32_t* Vs = sm + 2 * KSTG;           // [2][128][VS_PAD]
    uint32_t* Ps = sm + 2 * (KSTG + VSTG);  // [128][PS_PAD]
    const uint32_t ksB = (uint32_t)__cvta_generic_to_shared(Ks);
    const uint32_t vsB = (uint32_t)__cvta_generic_to_shared(Vs);

    const int tid  = threadIdx.x;
    const int lane = tid & 31;
    const int warp = tid >> 5;
    const int r4 = lane >> 2, q4 = lane & 3;
    const int bh = blockIdx.y;
    const int b  = bh >> 4;
    const int hh = bh & 15;
    const int qbase = blockIdx.x * 128;
    const int wrow  = warp * 16;

    const float* qp = qkv + ((size_t)(b * SEQL + qbase + wrow)) * LDQKV + hh * DK;
    const float* kbase = qkv + (size_t)b * SEQL * LDQKV + DMODEL + hh * DK;
    const float* vbase = qkv + (size_t)b * SEQL * LDQKV + 2 * DMODEL + hh * DK;

    uint32_t qf[8][4];
    #pragma unroll
    for (int kk = 0; kk < 8; kk++) {
        qf[kk][0] = __float_as_uint(qp[(size_t)r4       * LDQKV + kk * 8 + q4    ]);
        qf[kk][1] = __float_as_uint(qp[(size_t)(r4 + 8) * LDQKV + kk * 8 + q4    ]);
        qf[kk][2] = __float_as_uint(qp[(size_t)r4       * LDQKV + kk * 8 + q4 + 4]);
        qf[kk][3] = __float_as_uint(qp[(size_t)(r4 + 8) * LDQKV + kk * 8 + q4 + 4]);
    }

    float oacc[8][4];
    #pragma unroll
    for (int nf = 0; nf < 8; nf++)
        #pragma unroll
        for (int r = 0; r < 4; r++) oacc[nf][r] = 0.f;

    float m0 = -1e30f, m8 = -1e30f, l0 = 0.f, l8 = 0.f;

    {
        #pragma unroll
        for (int i = 0; i < 8; i++) {
            int f = tid + i * 256;
            int key = f >> 4, d4 = (f & 15) * 4;
            cp16(ksB + ((key * KS_PAD + d4) << 2), kbase + (size_t)key * LDQKV + d4);
            cp16(vsB + ((key * VS_PAD + d4) << 2), vbase + (size_t)key * LDQKV + d4);
        }
        cp_commit();
    }

    const int NT = SEQL / 128;
    for (int t = 0; t < NT; t++) {
        cp_wait0();
        __syncthreads();

        if (t + 1 < NT) {
            int st = (t + 1) & 1;
            int kt = (t + 1) * 128;
            #pragma unroll
            for (int i = 0; i < 8; i++) {
                int f = tid + i * 256;
                int key = f >> 4, d4 = (f & 15) * 4;
                cp16(ksB + ((st * KSTG + key * KS_PAD + d4) << 2),
                     kbase + (size_t)(kt + key) * LDQKV + d4);
                cp16(vsB + ((st * VSTG + key * VS_PAD + d4) << 2),
                     vbase + (size_t)(kt + key) * LDQKV + d4);
            }
            cp_commit();
        }

        const uint32_t* Ksl = Ks + (t & 1) * KSTG;
        const uint32_t* Vsl = Vs + (t & 1) * VSTG;

        float sacc[16][4];
        #pragma unroll
        for (int nf = 0; nf < 16; nf++)
            #pragma unroll
            for (int r = 0; r < 4; r++) sacc[nf][r] = 0.f;

        #pragma unroll
        for (int kk = 0; kk < 8; kk++)
            #pragma unroll
            for (int nf = 0; nf < 16; nf++) {
                uint32_t b0 = Ksl[(nf * 8 + r4) * KS_PAD + kk * 8 + q4];
                uint32_t b1 = Ksl[(nf * 8 + r4) * KS_PAD + kk * 8 + q4 + 4];
                mma_tf32(sacc[nf], qf[kk][0], qf[kk][1], qf[kk][2], qf[kk][3], b0, b1);
            }
        #pragma unroll
        for (int nf = 0; nf < 16; nf++) {
            sacc[nf][0] *= 0.125f; sacc[nf][1] *= 0.125f;
            sacc[nf][2] *= 0.125f; sacc[nf][3] *= 0.125f;
        }

        float mx0 = -1e30f, mx8 = -1e30f;
        #pragma unroll
        for (int nf = 0; nf < 16; nf++) {
            mx0 = fmaxf(mx0, fmaxf(sacc[nf][0], sacc[nf][1]));
            mx8 = fmaxf(mx8, fmaxf(sacc[nf][2], sacc[nf][3]));
        }
        mx0 = fmaxf(mx0, __shfl_xor_sync(0xffffffffu, mx0, 1));
        mx0 = fmaxf(mx0, __shfl_xor_sync(0xffffffffu, mx0, 2));
        mx8 = fmaxf(mx8, __shfl_xor_sync(0xffffffffu, mx8, 1));
        mx8 = fmaxf(mx8, __shfl_xor_sync(0xffffffffu, mx8, 2));

        float mn0 = fmaxf(m0, mx0), mn8 = fmaxf(m8, mx8);
        float sc0 = __expf(m0 - mn0), sc8 = __expf(m8 - mn8);
        m0 = mn0; m8 = mn8;
        l0 *= sc0; l8 *= sc8;
        #pragma unroll
        for (int nf = 0; nf < 8; nf++) {
            oacc[nf][0] *= sc0; oacc[nf][1] *= sc0;
            oacc[nf][2] *= sc8; oacc[nf][3] *= sc8;
        }

        float rs0 = 0.f, rs8 = 0.f;
        uint32_t* pw0 = Ps + (wrow + r4) * PS_PAD;
        uint32_t* pw8 = Ps + (wrow + r4 + 8) * PS_PAD;
        #pragma unroll
        for (int nf = 0; nf < 16; nf++) {
            float p0 = __expf(sacc[nf][0] - m0);
            float p1 = __expf(sacc[nf][1] - m0);
            float p2 = __expf(sacc[nf][2] - m8);
            float p3 = __expf(sacc[nf][3] - m8);
            rs0 += p0 + p1; rs8 += p2 + p3;
            int col = nf * 8 + 2 * q4;
            pw0[col] = __float_as_uint(p0); pw0[col + 1] = __float_as_uint(p1);
            pw8[col] = __float_as_uint(p2); pw8[col + 1] = __float_as_uint(p3);
        }
        rs0 += __shfl_xor_sync(0xffffffffu, rs0, 1);
        rs0 += __shfl_xor_sync(0xffffffffu, rs0, 2);
        rs8 += __shfl_xor_sync(0xffffffffu, rs8, 1);
        rs8 += __shfl_xor_sync(0xffffffffu, rs8, 2);
        l0 += rs0; l8 += rs8;
        __syncwarp();

        #pragma unroll
        for (int kk = 0; kk < 16; kk++) {
            uint32_t a0 = Ps[(wrow + r4)     * PS_PAD + kk * 8 + q4];
            uint32_t a1 = Ps[(wrow + r4 + 8) * PS_PAD + kk * 8 + q4];
            uint32_t a2 = Ps[(wrow + r4)     * PS_PAD + kk * 8 + q4 + 4];
            uint32_t a3 = Ps[(wrow + r4 + 8) * PS_PAD + kk * 8 + q4 + 4];
            #pragma unroll
            for (int nf = 0; nf < 8; nf++) {
                uint32_t b0 = Vsl[(kk * 8 + q4)     * VS_PAD + nf * 8 + r4];
                uint32_t b1 = Vsl[(kk * 8 + q4 + 4) * VS_PAD + nf * 8 + r4];
                mma_tf32(oacc[nf], a0, a1, a2, a3, b0, b1);
            }
        }
    }

    const float inv0 = 1.f / l0, inv8 = 1.f / l8;
    const int lg0 = qbase + wrow + r4;
    const int lg8 = lg0 + 8;
    #pragma unroll
    for (int nf = 0; nf < 8; nf++) {
        int d = nf * 8 + 2 * q4;
        int row0 = hh * 128 + (lg0 >> 4), col0 = (lg0 & 15) * 64 + d;
        int row8 = hh * 128 + (lg8 >> 4), col8 = (lg8 & 15) * 64 + d;
        *(float2*)(o_out + ((size_t)(b * SEQL + row0)) * DMODEL + col0) =
            make_float2(oacc[nf][0] * inv0, oacc[nf][1] * inv0);
        *(float2*)(o_out + ((size_t)(b * SEQL + row8)) * DMODEL + col8) =
            make_float2(oacc[nf][2] * inv8, oacc[nf][3] * inv8);
    }
}

// ---------------- residual add + LayerNorm ----------------------------------
__global__ __launch_bounds__(256) void add_ln_kernel(
    const float* __restrict__ a, const float* __restrict__ b,
    const float* __restrict__ g, const float* __restrict__ beta,
    float* __restrict__ out)
{
    const int row = blockIdx.x;
    const int tid = threadIdx.x;
    const float* ar = a + (size_t)row * DMODEL;
    const float* br = b + (size_t)row * DMODEL;

    float x[4];
    float sum = 0.f, sq = 0.f;
    #pragma unroll
    for (int i = 0; i < 4; i++) {
        int c = tid + i * 256;
        x[i] = ar[c] + br[c];
        sum += x[i]; sq += x[i] * x[i];
    }
    #pragma unroll
    for (int off = 16; off; off >>= 1) {
        sum += __shfl_xor_sync(0xffffffffu, sum, off);
        sq  += __shfl_xor_sync(0xffffffffu, sq, off);
    }
    __shared__ float ssum[8], ssq[8];
    const int wid = tid >> 5;
    if ((tid & 31) == 0) { ssum[wid] = sum; ssq[wid] = sq; }
    __syncthreads();
    sum = 0.f; sq = 0.f;
    #pragma unroll
    for (int w = 0; w < 8; w++) { sum += ssum[w]; sq += ssq[w]; }

    const float mean = sum * (1.f / DMODEL);
    const float var  = sq * (1.f / DMODEL) - mean * mean;
    const float rstd = rsqrtf(var + 1e-5f);

    float* orow = out + (size_t)row * DMODEL;
    #pragma unroll
    for (int i = 0; i < 4; i++) {
        int c = tid + i * 256;
        orow[c] = (x[i] - mean) * rstd * g[c] + beta[c];
    }
}

__global__ void concat_bias(const float* a, const float* b, const float* c, float* o)
{
    int i = blockIdx.x * 256 + threadIdx.x;
    if (i < DMODEL) {
        o[i] = a[i]; o[i + DMODEL] = b[i]; o[i + 2 * DMODEL] = c[i];
    }
}

// ---------------- launch ----------------------------------------------------
extern "C" void kernel_launch(void* const* d_in, const int* in_sizes, int n_in,
                              void* d_out, int out_size)
{
    const float* x    = (const float*)d_in[0];
    const float* Wq   = (const float*)d_in[1];
    const float* bq   = (const float*)d_in[2];
    const float* Wk   = (const float*)d_in[3];
    const float* bk   = (const float*)d_in[4];
    const float* Wv   = (const float*)d_in[5];
    const float* bv   = (const float*)d_in[6];
    const float* Wo   = (const float*)d_in[7];
    const float* bo   = (const float*)d_in[8];
    const float* W1   = (const float*)d_in[9];
    const float* b1   = (const float*)d_in[10];
    const float* W2   = (const float*)d_in[11];
    const float* b2   = (const float*)d_in[12];
    const float* g1   = (const float*)d_in[13];
    const float* bt1  = (const float*)d_in[14];
    const float* g2   = (const float*)d_in[15];
    const float* bt2  = (const float*)d_in[16];
    float* out = (float*)d_out;

    float *qkv, *attnv, *tmp, *x1, *ff, *tmp2, *bias3;
    cudaGetSymbolAddress((void**)&qkv,   g_qkv);
    cudaGetSymbolAddress((void**)&attnv, g_attnv);
    cudaGetSymbolAddress((void**)&tmp,   g_tmp);
    cudaGetSymbolAddress((void**)&x1,    g_x1);
    cudaGetSymbolAddress((void**)&ff,    g_ff);
    cudaGetSymbolAddress((void**)&tmp2,  g_tmp2);
    cudaGetSymbolAddress((void**)&bias3, g_bias3);

    cudaFuncSetAttribute(tgemm_bias, cudaFuncAttributeMaxDynamicSharedMemorySize,
                         GEMM_SMEM_BYTES);
    cudaFuncSetAttribute(attn_tc, cudaFuncAttributeMaxDynamicSharedMemorySize,
                         ATT_SMEM_BYTES);

    concat_bias<<<4, 256>>>(bq, bk, bv, bias3);

    // fused QKV projection: [4096 x 1024] @ [1024 x 3072]
    dim3 gQKV(3 * DMODEL / 128, TOKENS / 128);  // (24, 32)
    tgemm_bias<<<gQKV, 256, GEMM_SMEM_BYTES>>>(
        x, Wq, Wk, Wv, bias3, qkv, TOKENS, 3 * DMODEL, DMODEL, DMODEL, 0);

    // tensor-core flash attention (reference's no-transpose reshape epilogue)
    dim3 gA(SEQL / 128, BATCH * NHEADS);        // (16, 32)
    attn_tc<<<gA, 256, ATT_SMEM_BYTES>>>(qkv, attnv);

    // output projection + residual LN
    dim3 gD(DMODEL / 128, TOKENS / 128);        // (8, 32)
    tgemm_bias<<<gD, 256, GEMM_SMEM_BYTES>>>(
        attnv, Wo, nullptr, nullptr, bo, tmp, TOKENS, DMODEL, DMODEL, DMODEL, 0);
    add_ln_kernel<<<TOKENS, 256>>>(tmp, x, g1, bt1, x1);

    // FFN
    dim3 gF(DFF / 128, TOKENS / 128);           // (32, 32)
    tgemm_bias<<<gF, 256, GEMM_SMEM_BYTES>>>(
        x1, W1, nullptr, nullptr, b1, ff, TOKENS, DFF, DMODEL, DFF, 1);
    tgemm_bias<<<gD, 256, GEMM_SMEM_BYTES>>>(
        ff, W2, nullptr, nullptr, b2, tmp2, TOKENS, DMODEL, DFF, DMODEL, 0);
    add_ln_kernel<<<TOKENS, 256>>>(tmp2, x1, g2, bt2, out);
}

// round 11
// speedup vs baseline: 1.0683x; 1.0451x over previous
#include <cuda_runtime.h>
#include <math.h>
#include <stdint.h>

#define BATCH 2
#define SEQL  2048
#define DMODEL 1024
#define NHEADS 16
#define DK    64
#define DFF   4096
#define TOKENS (BATCH*SEQL)   // 4096

// ---------------- scratch (device globals: allocation-guard safe) -----------
__device__ float g_qkv[TOKENS*3*DMODEL];
__device__ float g_attnv[TOKENS*DMODEL];
__device__ float g_tmp[TOKENS*DMODEL];
__device__ float g_x1[TOKENS*DMODEL];
__device__ float g_ff[TOKENS*DFF];
__device__ float g_tmp2[TOKENS*DMODEL];
__device__ float g_bias3[3*DMODEL];

// ---------------- helpers ----------------------------------------------------
__device__ __forceinline__ void mma_tf32(float c[4],
    uint32_t a0, uint32_t a1, uint32_t a2, uint32_t a3,
    uint32_t b0, uint32_t b1)
{
    asm volatile(
        "mma.sync.aligned.m16n8k8.row.col.f32.tf32.tf32.f32 "
        "{%0,%1,%2,%3}, {%4,%5,%6,%7}, {%8,%9}, {%0,%1,%2,%3};"
        : "+f"(c[0]), "+f"(c[1]), "+f"(c[2]), "+f"(c[3])
        : "r"(a0), "r"(a1), "r"(a2), "r"(a3), "r"(b0), "r"(b1));
}

__device__ __forceinline__ void ldsm4(uint32_t& r0, uint32_t& r1,
                                      uint32_t& r2, uint32_t& r3, uint32_t addr)
{
    asm volatile("ldmatrix.sync.aligned.m8n8.x4.shared.b16 {%0,%1,%2,%3}, [%4];"
                 : "=r"(r0), "=r"(r1), "=r"(r2), "=r"(r3) : "r"(addr));
}

__device__ __forceinline__ void cp16(uint32_t dst, const void* src) {
    asm volatile("cp.async.cg.shared.global [%0], [%1], 16;" :: "r"(dst), "l"(src));
}
__device__ __forceinline__ void cp_commit() { asm volatile("cp.async.commit_group;"); }
__device__ __forceinline__ void cp_wait0()  { asm volatile("cp.async.wait_group 0;"); }

// ---------------- TF32 GEMM, 128x128 tile, BK=32, 2 CTAs/SM, ldmatrix A -----
// 256 thr (8 warps), warp tile 64x32 (4x4 m16n8k8). A-fragments via
// ldmatrix.x4 (1 instr for 4 regs); B via padded LDS pairs. Raw fp32 bits ->
// tf32 HW truncation.
#define A_PAD 36
#define B_PAD 136
#define ASTG (128*A_PAD)
#define BSTG (32*B_PAD)
#define GEMM_SMEM_BYTES (2*(ASTG+BSTG)*4)   // ~70 KB

__global__ __launch_bounds__(256, 2) void tgemm_bias(
    const float* __restrict__ A,
    const float* __restrict__ B0, const float* __restrict__ B1,
    const float* __restrict__ B2,
    const float* __restrict__ bias, float* __restrict__ C,
    int M, int N, int K, int ldb, int gelu)
{
    extern __shared__ uint32_t sg[];
    uint32_t* As = sg;            // [2][128][A_PAD]
    uint32_t* Bs = sg + 2*ASTG;   // [2][32][B_PAD]
    const uint32_t asB = (uint32_t)__cvta_generic_to_shared(As);
    const uint32_t bsB = (uint32_t)__cvta_generic_to_shared(Bs);

    const int tid  = threadIdx.x;
    const int lane = tid & 31;
    const int warp = tid >> 5;
    const int r4 = lane >> 2, q4 = lane & 3;
    const int wm = (warp & 1) * 64;     // 2 warps in M
    const int wn = (warp >> 1) * 32;    // 4 warps in N
    const int rowBase = blockIdx.y * 128;
    const int colBase = blockIdx.x * 128;

    // fused-QKV column select (each 128-col block lies in one source matrix)
    const float* Bw = B0;
    int cb = colBase;
    if (B1 && colBase >= ldb) { Bw = B1; cb = colBase - ldb; }
    if (B2 && colBase >= 2 * ldb) { Bw = B2; cb = colBase - 2 * ldb; }

    // ldmatrix lane-address components for A fragments:
    // row = wm + mf*16 + (lane&15), col = kk*8 + ((lane&16)?4:0)
    const int lmRow = wm + (lane & 15);
    const int lmCol = (lane & 16) ? 4 : 0;

    float acc[4][4][4];
    #pragma unroll
    for (int i = 0; i < 4; i++)
        #pragma unroll
        for (int j = 0; j < 4; j++)
            #pragma unroll
            for (int r = 0; r < 4; r++) acc[i][j][r] = 0.f;

    const int NC = K / 32;

    // stage 0
    {
        #pragma unroll
        for (int i = 0; i < 4; i++) {
            int f = tid + i * 256;
            int r = f >> 3, c4 = (f & 7) * 4;
            cp16(asB + ((r * A_PAD + c4) << 2), A + (size_t)(rowBase + r) * K + c4);
        }
        #pragma unroll
        for (int i = 0; i < 4; i++) {
            int f = tid + i * 256;
            int r = f >> 5, c4 = (f & 31) * 4;
            cp16(bsB + ((r * B_PAD + c4) << 2), Bw + (size_t)r * ldb + cb + c4);
        }
        cp_commit();
    }

    for (int ic = 0; ic < NC; ic++) {
        cp_wait0();
        __syncthreads();

        if (ic + 1 < NC) {
            int st = (ic + 1) & 1;
            int k0 = (ic + 1) * 32;
            #pragma unroll
            for (int i = 0; i < 4; i++) {
                int f = tid + i * 256;
                int r = f >> 3, c4 = (f & 7) * 4;
                cp16(asB + ((st * ASTG + r * A_PAD + c4) << 2),
                     A + (size_t)(rowBase + r) * K + k0 + c4);
            }
            #pragma unroll
            for (int i = 0; i < 4; i++) {
                int f = tid + i * 256;
                int r = f >> 5, c4 = (f & 31) * 4;
                cp16(bsB + ((st * BSTG + r * B_PAD + c4) << 2),
                     Bw + (size_t)(k0 + r) * ldb + cb + c4);
            }
            cp_commit();
        }

        const uint32_t aBase = asB + (((ic & 1) * ASTG + lmRow * A_PAD + lmCol) << 2);
        const uint32_t* Bsl = Bs + (ic & 1) * BSTG;

        #pragma unroll
        for (int kk = 0; kk < 4; kk++) {
            uint32_t af[4][4], bf[4][2];
            #pragma unroll
            for (int mf = 0; mf < 4; mf++)
                ldsm4(af[mf][0], af[mf][1], af[mf][2], af[mf][3],
                      aBase + ((mf * 16 * A_PAD + kk * 8) << 2));
            #pragma unroll
            for (int nf = 0; nf < 4; nf++) {
                int cc = wn + nf * 8 + r4;
                int rr = kk * 8 + q4;
                bf[nf][0] = Bsl[rr * B_PAD + cc];
                bf[nf][1] = Bsl[(rr + 4) * B_PAD + cc];
            }
            #pragma unroll
            for (int mf = 0; mf < 4; mf++)
                #pragma unroll
                for (int nf = 0; nf < 4; nf++)
                    mma_tf32(acc[mf][nf], af[mf][0], af[mf][1], af[mf][2], af[mf][3],
                             bf[nf][0], bf[nf][1]);
        }
        __syncthreads();
    }

    #pragma unroll
    for (int mf = 0; mf < 4; mf++) {
        #pragma unroll
        for (int nf = 0; nf < 4; nf++) {
            int row = rowBase + wm + mf * 16 + r4;
            int col = colBase + wn + nf * 8 + 2 * q4;
            float v0 = acc[mf][nf][0] + bias[col];
            float v1 = acc[mf][nf][1] + bias[col + 1];
            float v2 = acc[mf][nf][2] + bias[col];
            float v3 = acc[mf][nf][3] + bias[col + 1];
            if (gelu) {
                v0 = 0.5f * v0 * (1.f + erff(v0 * 0.70710678118654752f));
                v1 = 0.5f * v1 * (1.f + erff(v1 * 0.70710678118654752f));
                v2 = 0.5f * v2 * (1.f + erff(v2 * 0.70710678118654752f));
                v3 = 0.5f * v3 * (1.f + erff(v3 * 0.70710678118654752f));
            }
            *(float2*)(C + (size_t)row * N + col)       = make_float2(v0, v1);
            *(float2*)(C + (size_t)(row + 8) * N + col) = make_float2(v2, v3);
        }
    }
}

// ---------------- tensor-core flash attention, cp.async double-buffered -----
#define KS_PAD 68
#define VS_PAD 72
#define PS_PAD 132
#define KSTG (128*KS_PAD)
#define VSTG (128*VS_PAD)
#define ATT_SMEM_BYTES ((2*KSTG + 2*VSTG + 128*PS_PAD) * 4)
#define LDQKV (3*DMODEL)

__global__ __launch_bounds__(256, 1) void attn_tc(
    const float* __restrict__ qkv, float* __restrict__ o_out)
{
    extern __shared__ uint32_t sm[];
    uint32_t* Ks = sm;                      // [2][128][KS_PAD]
    uint32_t* Vs = sm + 2 * KSTG;           // [2][128][VS_PAD]
    uint32_t* Ps = sm + 2 * (KSTG + VSTG);  // [128][PS_PAD]
    const uint32_t ksB = (uint32_t)__cvta_generic_to_shared(Ks);
    const uint32_t vsB = (uint32_t)__cvta_generic_to_shared(Vs);

    const int tid  = threadIdx.x;
    const int lane = tid & 31;
    const int warp = tid >> 5;
    const int r4 = lane >> 2, q4 = lane & 3;
    const int bh = blockIdx.y;
    const int b  = bh >> 4;
    const int hh = bh & 15;
    const int qbase = blockIdx.x * 128;
    const int wrow  = warp * 16;

    const float* qp = qkv + ((size_t)(b * SEQL + qbase + wrow)) * LDQKV + hh * DK;
    const float* kbase = qkv + (size_t)b * SEQL * LDQKV + DMODEL + hh * DK;
    const float* vbase = qkv + (size_t)b * SEQL * LDQKV + 2 * DMODEL + hh * DK;

    uint32_t qf[8][4];
    #pragma unroll
    for (int kk = 0; kk < 8; kk++) {
        qf[kk][0] = __float_as_uint(qp[(size_t)r4       * LDQKV + kk * 8 + q4    ]);
        qf[kk][1] = __float_as_uint(qp[(size_t)(r4 + 8) * LDQKV + kk * 8 + q4    ]);
        qf[kk][2] = __float_as_uint(qp[(size_t)r4       * LDQKV + kk * 8 + q4 + 4]);
        qf[kk][3] = __float_as_uint(qp[(size_t)(r4 + 8) * LDQKV + kk * 8 + q4 + 4]);
    }

    float oacc[8][4];
    #pragma unroll
    for (int nf = 0; nf < 8; nf++)
        #pragma unroll
        for (int r = 0; r < 4; r++) oacc[nf][r] = 0.f;

    float m0 = -1e30f, m8 = -1e30f, l0 = 0.f, l8 = 0.f;

    {
        #pragma unroll
        for (int i = 0; i < 8; i++) {
            int f = tid + i * 256;
            int key = f >> 4, d4 = (f & 15) * 4;
            cp16(ksB + ((key * KS_PAD + d4) << 2), kbase + (size_t)key * LDQKV + d4);
            cp16(vsB + ((key * VS_PAD + d4) << 2), vbase + (size_t)key * LDQKV + d4);
        }
        cp_commit();
    }

    const int NT = SEQL / 128;
    for (int t = 0; t < NT; t++) {
        cp_wait0();
        __syncthreads();

        if (t + 1 < NT) {
            int st = (t + 1) & 1;
            int kt = (t + 1) * 128;
            #pragma unroll
            for (int i = 0; i < 8; i++) {
                int f = tid + i * 256;
                int key = f >> 4, d4 = (f & 15) * 4;
                cp16(ksB + ((st * KSTG + key * KS_PAD + d4) << 2),
                     kbase + (size_t)(kt + key) * LDQKV + d4);
                cp16(vsB + ((st * VSTG + key * VS_PAD + d4) << 2),
                     vbase + (size_t)(kt + key) * LDQKV + d4);
            }
            cp_commit();
        }

        const uint32_t* Ksl = Ks + (t & 1) * KSTG;
        const uint32_t* Vsl = Vs + (t & 1) * VSTG;

        float sacc[16][4];
        #pragma unroll
        for (int nf = 0; nf < 16; nf++)
            #pragma unroll
            for (int r = 0; r < 4; r++) sacc[nf][r] = 0.f;

        #pragma unroll
        for (int kk = 0; kk < 8; kk++)
            #pragma unroll
            for (int nf = 0; nf < 16; nf++) {
                uint32_t b0 = Ksl[(nf * 8 + r4) * KS_PAD + kk * 8 + q4];
                uint32_t b1 = Ksl[(nf * 8 + r4) * KS_PAD + kk * 8 + q4 + 4];
                mma_tf32(sacc[nf], qf[kk][0], qf[kk][1], qf[kk][2], qf[kk][3], b0, b1);
            }
        #pragma unroll
        for (int nf = 0; nf < 16; nf++) {
            sacc[nf][0] *= 0.125f; sacc[nf][1] *= 0.125f;
            sacc[nf][2] *= 0.125f; sacc[nf][3] *= 0.125f;
        }

        float mx0 = -1e30f, mx8 = -1e30f;
        #pragma unroll
        for (int nf = 0; nf < 16; nf++) {
            mx0 = fmaxf(mx0, fmaxf(sacc[nf][0], sacc[nf][1]));
            mx8 = fmaxf(mx8, fmaxf(sacc[nf][2], sacc[nf][3]));
        }
        mx0 = fmaxf(mx0, __shfl_xor_sync(0xffffffffu, mx0, 1));
        mx0 = fmaxf(mx0, __shfl_xor_sync(0xffffffffu, mx0, 2));
        mx8 = fmaxf(mx8, __shfl_xor_sync(0xffffffffu, mx8, 1));
        mx8 = fmaxf(mx8, __shfl_xor_sync(0xffffffffu, mx8, 2));

        float mn0 = fmaxf(m0, mx0), mn8 = fmaxf(m8, mx8);
        float sc0 = __expf(m0 - mn0), sc8 = __expf(m8 - mn8);
        m0 = mn0; m8 = mn8;
        l0 *= sc0; l8 *= sc8;
        #pragma unroll
        for (int nf = 0; nf < 8; nf++) {
            oacc[nf][0] *= sc0; oacc[nf][1] *= sc0;
            oacc[nf][2] *= sc8; oacc[nf][3] *= sc8;
        }

        float rs0 = 0.f, rs8 = 0.f;
        uint32_t* pw0 = Ps + (wrow + r4) * PS_PAD;
        uint32_t* pw8 = Ps + (wrow + r4 + 8) * PS_PAD;
        #pragma unroll
        for (int nf = 0; nf < 16; nf++) {
            float p0 = __expf(sacc[nf][0] - m0);
            float p1 = __expf(sacc[nf][1] - m0);
            float p2 = __expf(sacc[nf][2] - m8);
            float p3 = __expf(sacc[nf][3] - m8);
            rs0 += p0 + p1; rs8 += p2 + p3;
            int col = nf * 8 + 2 * q4;
            pw0[col] = __float_as_uint(p0); pw0[col + 1] = __float_as_uint(p1);
            pw8[col] = __float_as_uint(p2); pw8[col + 1] = __float_as_uint(p3);
        }
        rs0 += __shfl_xor_sync(0xffffffffu, rs0, 1);
        rs0 += __shfl_xor_sync(0xffffffffu, rs0, 2);
        rs8 += __shfl_xor_sync(0xffffffffu, rs8, 1);
        rs8 += __shfl_xor_sync(0xffffffffu, rs8, 2);
        l0 += rs0; l8 += rs8;
        __syncwarp();

        #pragma unroll
        for (int kk = 0; kk < 16; kk++) {
            uint32_t a0 = Ps[(wrow + r4)     * PS_PAD + kk * 8 + q4];
            uint32_t a1 = Ps[(wrow + r4 + 8) * PS_PAD + kk * 8 + q4];
            uint32_t a2 = Ps[(wrow + r4)     * PS_PAD + kk * 8 + q4 + 4];
            uint32_t a3 = Ps[(wrow + r4 + 8) * PS_PAD + kk * 8 + q4 + 4];
            #pragma unroll
            for (int nf = 0; nf < 8; nf++) {
                uint32_t b0 = Vsl[(kk * 8 + q4)     * VS_PAD + nf * 8 + r4];
                uint32_t b1 = Vsl[(kk * 8 + q4 + 4) * VS_PAD + nf * 8 + r4];
                mma_tf32(oacc[nf], a0, a1, a2, a3, b0, b1);
            }
        }
    }

    const float inv0 = 1.f / l0, inv8 = 1.f / l8;
    const int lg0 = qbase + wrow + r4;
    const int lg8 = lg0 + 8;
    #pragma unroll
    for (int nf = 0; nf < 8; nf++) {
        int d = nf * 8 + 2 * q4;
        int row0 = hh * 128 + (lg0 >> 4), col0 = (lg0 & 15) * 64 + d;
        int row8 = hh * 128 + (lg8 >> 4), col8 = (lg8 & 15) * 64 + d;
        *(float2*)(o_out + ((size_t)(b * SEQL + row0)) * DMODEL + col0) =
            make_float2(oacc[nf][0] * inv0, oacc[nf][1] * inv0);
        *(float2*)(o_out + ((size_t)(b * SEQL + row8)) * DMODEL + col8) =
            make_float2(oacc[nf][2] * inv8, oacc[nf][3] * inv8);
    }
}

// ---------------- residual add + LayerNorm ----------------------------------
__global__ __launch_bounds__(256) void add_ln_kernel(
    const float* __restrict__ a, const float* __restrict__ b,
    const float* __restrict__ g, const float* __restrict__ beta,
    float* __restrict__ out)
{
    const int row = blockIdx.x;
    const int tid = threadIdx.x;
    const float* ar = a + (size_t)row * DMODEL;
    const float* br = b + (size_t)row * DMODEL;

    float x[4];
    float sum = 0.f, sq = 0.f;
    #pragma unroll
    for (int i = 0; i < 4; i++) {
        int c = tid + i * 256;
        x[i] = ar[c] + br[c];
        sum += x[i]; sq += x[i] * x[i];
    }
    #pragma unroll
    for (int off = 16; off; off >>= 1) {
        sum += __shfl_xor_sync(0xffffffffu, sum, off);
        sq  += __shfl_xor_sync(0xffffffffu, sq, off);
    }
    __shared__ float ssum[8], ssq[8];
    const int wid = tid >> 5;
    if ((tid & 31) == 0) { ssum[wid] = sum; ssq[wid] = sq; }
    __syncthreads();
    sum = 0.f; sq = 0.f;
    #pragma unroll
    for (int w = 0; w < 8; w++) { sum += ssum[w]; sq += ssq[w]; }

    const float mean = sum * (1.f / DMODEL);
    const float var  = sq * (1.f / DMODEL) - mean * mean;
    const float rstd = rsqrtf(var + 1e-5f);

    float* orow = out + (size_t)row * DMODEL;
    #pragma unroll
    for (int i = 0; i < 4; i++) {
        int c = tid + i * 256;
        orow[c] = (x[i] - mean) * rstd * g[c] + beta[c];
    }
}

__global__ void concat_bias(const float* a, const float* b, const float* c, float* o)
{
    int i = blockIdx.x * 256 + threadIdx.x;
    if (i < DMODEL) {
        o[i] = a[i]; o[i + DMODEL] = b[i]; o[i + 2 * DMODEL] = c[i];
    }
}

// ---------------- launch ----------------------------------------------------
extern "C" void kernel_launch(void* const* d_in, const int* in_sizes, int n_in,
                              void* d_out, int out_size)
{
    const float* x    = (const float*)d_in[0];
    const float* Wq   = (const float*)d_in[1];
    const float* bq   = (const float*)d_in[2];
    const float* Wk   = (const float*)d_in[3];
    const float* bk   = (const float*)d_in[4];
    const float* Wv   = (const float*)d_in[5];
    const float* bv   = (const float*)d_in[6];
    const float* Wo   = (const float*)d_in[7];
    const float* bo   = (const float*)d_in[8];
    const float* W1   = (const float*)d_in[9];
    const float* b1   = (const float*)d_in[10];
    const float* W2   = (const float*)d_in[11];
    const float* b2   = (const float*)d_in[12];
    const float* g1   = (const float*)d_in[13];
    const float* bt1  = (const float*)d_in[14];
    const float* g2   = (const float*)d_in[15];
    const float* bt2  = (const float*)d_in[16];
    float* out = (float*)d_out;

    float *qkv, *attnv, *tmp, *x1, *ff, *tmp2, *bias3;
    cudaGetSymbolAddress((void**)&qkv,   g_qkv);
    cudaGetSymbolAddress((void**)&attnv, g_attnv);
    cudaGetSymbolAddress((void**)&tmp,   g_tmp);
    cudaGetSymbolAddress((void**)&x1,    g_x1);
    cudaGetSymbolAddress((void**)&ff,    g_ff);
    cudaGetSymbolAddress((void**)&tmp2,  g_tmp2);
    cudaGetSymbolAddress((void**)&bias3, g_bias3);

    cudaFuncSetAttribute(tgemm_bias, cudaFuncAttributeMaxDynamicSharedMemorySize,
                         GEMM_SMEM_BYTES);
    cudaFuncSetAttribute(attn_tc, cudaFuncAttributeMaxDynamicSharedMemorySize,
                         ATT_SMEM_BYTES);

    concat_bias<<<4, 256>>>(bq, bk, bv, bias3);

    // fused QKV projection: [4096 x 1024] @ [1024 x 3072]
    dim3 gQKV(3 * DMODEL / 128, TOKENS / 128);  // (24, 32)
    tgemm_bias<<<gQKV, 256, GEMM_SMEM_BYTES>>>(
        x, Wq, Wk, Wv, bias3, qkv, TOKENS, 3 * DMODEL, DMODEL, DMODEL, 0);

    // tensor-core flash attention (reference's no-transpose reshape epilogue)
    dim3 gA(SEQL / 128, BATCH * NHEADS);        // (16, 32)
    attn_tc<<<gA, 256, ATT_SMEM_BYTES>>>(qkv, attnv);

    // output projection + residual LN
    dim3 gD(DMODEL / 128, TOKENS / 128);        // (8, 32)
    tgemm_bias<<<gD, 256, GEMM_SMEM_BYTES>>>(
        attnv, Wo, nullptr, nullptr, bo, tmp, TOKENS, DMODEL, DMODEL, DMODEL, 0);
    add_ln_kernel<<<TOKENS, 256>>>(tmp, x, g1, bt1, x1);

    // FFN
    dim3 gF(DFF / 128, TOKENS / 128);           // (32, 32)
    tgemm_bias<<<gF, 256, GEMM_SMEM_BYTES>>>(
        x1, W1, nullptr, nullptr, b1, ff, TOKENS, DFF, DMODEL, DFF, 1);
    tgemm_bias<<<gD, 256, GEMM_SMEM_BYTES>>>(
        ff, W2, nullptr, nullptr, b2, tmp2, TOKENS, DMODEL, DFF, DMODEL, 0);
    add_ln_kernel<<<TOKENS, 256>>>(tmp2, x1, g2, bt2, out);
}

// round 12
// speedup vs baseline: 1.0772x; 1.0084x over previous
#include <cuda_runtime.h>
#include <math.h>
#include <stdint.h>

#define BATCH 2
#define SEQL  2048
#define DMODEL 1024
#define NHEADS 16
#define DK    64
#define DFF   4096
#define TOKENS (BATCH*SEQL)   // 4096

// ---------------- scratch (device globals: allocation-guard safe) -----------
__device__ float g_qkv[TOKENS*3*DMODEL];
__device__ float g_attnv[TOKENS*DMODEL];
__device__ float g_tmp[TOKENS*DMODEL];
__device__ float g_x1[TOKENS*DMODEL];
__device__ float g_ff[TOKENS*DFF];
__device__ float g_tmp2[TOKENS*DMODEL];
__device__ float g_bias3[3*DMODEL];

// ---------------- helpers ----------------------------------------------------
__device__ __forceinline__ void mma_tf32(float c[4],
    uint32_t a0, uint32_t a1, uint32_t a2, uint32_t a3,
    uint32_t b0, uint32_t b1)
{
    asm volatile(
        "mma.sync.aligned.m16n8k8.row.col.f32.tf32.tf32.f32 "
        "{%0,%1,%2,%3}, {%4,%5,%6,%7}, {%8,%9}, {%0,%1,%2,%3};"
        : "+f"(c[0]), "+f"(c[1]), "+f"(c[2]), "+f"(c[3])
        : "r"(a0), "r"(a1), "r"(a2), "r"(a3), "r"(b0), "r"(b1));
}

__device__ __forceinline__ void ldsm4(uint32_t& r0, uint32_t& r1,
                                      uint32_t& r2, uint32_t& r3, uint32_t addr)
{
    asm volatile("ldmatrix.sync.aligned.m8n8.x4.shared.b16 {%0,%1,%2,%3}, [%4];"
                 : "=r"(r0), "=r"(r1), "=r"(r2), "=r"(r3) : "r"(addr));
}

__device__ __forceinline__ void cp16(uint32_t dst, const void* src) {
    asm volatile("cp.async.cg.shared.global [%0], [%1], 16;" :: "r"(dst), "l"(src));
}
__device__ __forceinline__ void cp_commit() { asm volatile("cp.async.commit_group;"); }
__device__ __forceinline__ void cp_wait0()  { asm volatile("cp.async.wait_group 0;"); }
__device__ __forceinline__ void cp_wait1()  { asm volatile("cp.async.wait_group 1;"); }

// ---------------- TF32 GEMM, 128x128 tile, BK=32, 3-stage, 2 CTAs/SM --------
// 256 thr (8 warps), warp tile 64x32 (4x4 m16n8k8), ldmatrix.x4 A-fragments,
// raw fp32 bits -> tf32 HW truncation. One __syncthreads per K-chunk.
#define A_PAD 36
#define B_PAD 136
#define ASTG (128*A_PAD)
#define BSTG (32*B_PAD)
#define STG_WORDS (ASTG+BSTG)
#define GM_STAGES 3
#define GEMM_SMEM_BYTES (GM_STAGES*STG_WORDS*4)   // ~105 KB

__global__ __launch_bounds__(256, 2) void tgemm_bias(
    const float* __restrict__ A,
    const float* __restrict__ B0, const float* __restrict__ B1,
    const float* __restrict__ B2,
    const float* __restrict__ bias, float* __restrict__ C,
    int M, int N, int K, int ldb, int gelu)
{
    extern __shared__ uint32_t sg[];
    const uint32_t smB = (uint32_t)__cvta_generic_to_shared(sg);

    const int tid  = threadIdx.x;
    const int lane = tid & 31;
    const int warp = tid >> 5;
    const int r4 = lane >> 2, q4 = lane & 3;
    const int wm = (warp & 1) * 64;     // 2 warps in M
    const int wn = (warp >> 1) * 32;    // 4 warps in N
    const int rowBase = blockIdx.y * 128;
    const int colBase = blockIdx.x * 128;

    // fused-QKV column select
    const float* Bw = B0;
    int cb = colBase;
    if (B1 && colBase >= ldb) { Bw = B1; cb = colBase - ldb; }
    if (B2 && colBase >= 2 * ldb) { Bw = B2; cb = colBase - 2 * ldb; }

    const int lmRow = wm + (lane & 15);
    const int lmCol = (lane & 16) ? 4 : 0;

    float acc[4][4][4];
    #pragma unroll
    for (int i = 0; i < 4; i++)
        #pragma unroll
        for (int j = 0; j < 4; j++)
            #pragma unroll
            for (int r = 0; r < 4; r++) acc[i][j][r] = 0.f;

    const int NC = K / 32;

    auto issue_chunk = [&](int j, int s) {
        const uint32_t base = smB + (uint32_t)(s * STG_WORDS) * 4u;
        const float* aSrc = A + (size_t)rowBase * K + j * 32;
        #pragma unroll
        for (int i = 0; i < 4; i++) {
            int f = tid + i * 256;
            int r = f >> 3, c4 = (f & 7) * 4;
            cp16(base + ((r * A_PAD + c4) << 2), aSrc + (size_t)r * K + c4);
        }
        const float* bSrc = Bw + (size_t)(j * 32) * ldb + cb;
        #pragma unroll
        for (int i = 0; i < 4; i++) {
            int f = tid + i * 256;
            int r = f >> 5, c4 = (f & 31) * 4;
            cp16(base + ((ASTG + r * B_PAD + c4) << 2), bSrc + (size_t)r * ldb + c4);
        }
        cp_commit();
    };

    issue_chunk(0, 0);
    issue_chunk(1, 1);

    for (int ic = 0; ic < NC; ic++) {
        if (ic + 1 < NC) cp_wait1(); else cp_wait0();
        __syncthreads();
        if (ic + 2 < NC) issue_chunk(ic + 2, (ic + 2) % GM_STAGES);

        const int s = ic % GM_STAGES;
        const uint32_t aBase = smB + (uint32_t)(s * STG_WORDS + lmRow * A_PAD + lmCol) * 4u;
        const uint32_t* Bsl = sg + s * STG_WORDS + ASTG;

        #pragma unroll
        for (int kk = 0; kk < 4; kk++) {
            uint32_t af[4][4], bf[4][2];
            #pragma unroll
            for (int mf = 0; mf < 4; mf++)
                ldsm4(af[mf][0], af[mf][1], af[mf][2], af[mf][3],
                      aBase + ((mf * 16 * A_PAD + kk * 8) << 2));
            #pragma unroll
            for (int nf = 0; nf < 4; nf++) {
                int cc = wn + nf * 8 + r4;
                int rr = kk * 8 + q4;
                bf[nf][0] = Bsl[rr * B_PAD + cc];
                bf[nf][1] = Bsl[(rr + 4) * B_PAD + cc];
            }
            #pragma unroll
            for (int mf = 0; mf < 4; mf++)
                #pragma unroll
                for (int nf = 0; nf < 4; nf++)
                    mma_tf32(acc[mf][nf], af[mf][0], af[mf][1], af[mf][2], af[mf][3],
                             bf[nf][0], bf[nf][1]);
        }
    }

    #pragma unroll
    for (int mf = 0; mf < 4; mf++) {
        #pragma unroll
        for (int nf = 0; nf < 4; nf++) {
            int row = rowBase + wm + mf * 16 + r4;
            int col = colBase + wn + nf * 8 + 2 * q4;
            float v0 = acc[mf][nf][0] + bias[col];
            float v1 = acc[mf][nf][1] + bias[col + 1];
            float v2 = acc[mf][nf][2] + bias[col];
            float v3 = acc[mf][nf][3] + bias[col + 1];
            if (gelu) {
                v0 = 0.5f * v0 * (1.f + erff(v0 * 0.70710678118654752f));
                v1 = 0.5f * v1 * (1.f + erff(v1 * 0.70710678118654752f));
                v2 = 0.5f * v2 * (1.f + erff(v2 * 0.70710678118654752f));
                v3 = 0.5f * v3 * (1.f + erff(v3 * 0.70710678118654752f));
            }
            *(float2*)(C + (size_t)row * N + col)       = make_float2(v0, v1);
            *(float2*)(C + (size_t)(row + 8) * N + col) = make_float2(v2, v3);
        }
    }
}

// ---------------- tensor-core flash attention, cp.async double-buffered -----
#define KS_PAD 68
#define VS_PAD 72
#define PS_PAD 132
#define KSTG (128*KS_PAD)
#define VSTG (128*VS_PAD)
#define ATT_SMEM_BYTES ((2*KSTG + 2*VSTG + 128*PS_PAD) * 4)
#define LDQKV (3*DMODEL)

__global__ __launch_bounds__(256, 1) void attn_tc(
    const float* __restrict__ qkv, float* __restrict__ o_out)
{
    extern __shared__ uint32_t sm[];
    uint32_t* Ks = sm;                      // [2][128][KS_PAD]
    uint32_t* Vs = sm + 2 * KSTG;           // [2][128][VS_PAD]
    uint32_t* Ps = sm + 2 * (KSTG + VSTG);  // [128][PS_PAD]
    const uint32_t ksB = (uint32_t)__cvta_generic_to_shared(Ks);
    const uint32_t vsB = (uint32_t)__cvta_generic_to_shared(Vs);

    const int tid  = threadIdx.x;
    const int lane = tid & 31;
    const int warp = tid >> 5;
    const int r4 = lane >> 2, q4 = lane & 3;
    const int bh = blockIdx.y;
    const int b  = bh >> 4;
    const int hh = bh & 15;
    const int qbase = blockIdx.x * 128;
    const int wrow  = warp * 16;

    const float* qp = qkv + ((size_t)(b * SEQL + qbase + wrow)) * LDQKV + hh * DK;
    const float* kbase = qkv + (size_t)b * SEQL * LDQKV + DMODEL + hh * DK;
    const float* vbase = qkv + (size_t)b * SEQL * LDQKV + 2 * DMODEL + hh * DK;

    // Q pre-scaled by 1/sqrt(dk): exact (power of two), commutes with tf32 trunc
    uint32_t qf[8][4];
    #pragma unroll
    for (int kk = 0; kk < 8; kk++) {
        qf[kk][0] = __float_as_uint(qp[(size_t)r4       * LDQKV + kk * 8 + q4    ] * 0.125f);
        qf[kk][1] = __float_as_uint(qp[(size_t)(r4 + 8) * LDQKV + kk * 8 + q4    ] * 0.125f);
        qf[kk][2] = __float_as_uint(qp[(size_t)r4       * LDQKV + kk * 8 + q4 + 4] * 0.125f);
        qf[kk][3] = __float_as_uint(qp[(size_t)(r4 + 8) * LDQKV + kk * 8 + q4 + 4] * 0.125f);
    }

    float oacc[8][4];
    #pragma unroll
    for (int nf = 0; nf < 8; nf++)
        #pragma unroll
        for (int r = 0; r < 4; r++) oacc[nf][r] = 0.f;

    float m0 = -1e30f, m8 = -1e30f, l0 = 0.f, l8 = 0.f;

    {
        #pragma unroll
        for (int i = 0; i < 8; i++) {
            int f = tid + i * 256;
            int key = f >> 4, d4 = (f & 15) * 4;
            cp16(ksB + ((key * KS_PAD + d4) << 2), kbase + (size_t)key * LDQKV + d4);
            cp16(vsB + ((key * VS_PAD + d4) << 2), vbase + (size_t)key * LDQKV + d4);
        }
        cp_commit();
    }

    const int NT = SEQL / 128;
    for (int t = 0; t < NT; t++) {
        cp_wait0();
        __syncthreads();

        if (t + 1 < NT) {
            int st = (t + 1) & 1;
            int kt = (t + 1) * 128;
            #pragma unroll
            for (int i = 0; i < 8; i++) {
                int f = tid + i * 256;
                int key = f >> 4, d4 = (f & 15) * 4;
                cp16(ksB + ((st * KSTG + key * KS_PAD + d4) << 2),
                     kbase + (size_t)(kt + key) * LDQKV + d4);
                cp16(vsB + ((st * VSTG + key * VS_PAD + d4) << 2),
                     vbase + (size_t)(kt + key) * LDQKV + d4);
            }
            cp_commit();
        }

        const uint32_t* Ksl = Ks + (t & 1) * KSTG;
        const uint32_t* Vsl = Vs + (t & 1) * VSTG;

        float sacc[16][4];
        #pragma unroll
        for (int nf = 0; nf < 16; nf++)
            #pragma unroll
            for (int r = 0; r < 4; r++) sacc[nf][r] = 0.f;

        #pragma unroll
        for (int kk = 0; kk < 8; kk++)
            #pragma unroll
            for (int nf = 0; nf < 16; nf++) {
                uint32_t b0 = Ksl[(nf * 8 + r4) * KS_PAD + kk * 8 + q4];
                uint32_t b1 = Ksl[(nf * 8 + r4) * KS_PAD + kk * 8 + q4 + 4];
                mma_tf32(sacc[nf], qf[kk][0], qf[kk][1], qf[kk][2], qf[kk][3], b0, b1);
            }

        float mx0 = -1e30f, mx8 = -1e30f;
        #pragma unroll
        for (int nf = 0; nf < 16; nf++) {
            mx0 = fmaxf(mx0, fmaxf(sacc[nf][0], sacc[nf][1]));
            mx8 = fmaxf(mx8, fmaxf(sacc[nf][2], sacc[nf][3]));
        }
        mx0 = fmaxf(mx0, __shfl_xor_sync(0xffffffffu, mx0, 1));
        mx0 = fmaxf(mx0, __shfl_xor_sync(0xffffffffu, mx0, 2));
        mx8 = fmaxf(mx8, __shfl_xor_sync(0xffffffffu, mx8, 1));
        mx8 = fmaxf(mx8, __shfl_xor_sync(0xffffffffu, mx8, 2));

        float mn0 = fmaxf(m0, mx0), mn8 = fmaxf(m8, mx8);
        float sc0 = __expf(m0 - mn0), sc8 = __expf(m8 - mn8);
        m0 = mn0; m8 = mn8;
        l0 *= sc0; l8 *= sc8;
        #pragma unroll
        for (int nf = 0; nf < 8; nf++) {
            oacc[nf][0] *= sc0; oacc[nf][1] *= sc0;
            oacc[nf][2] *= sc8; oacc[nf][3] *= sc8;
        }

        float rs0 = 0.f, rs8 = 0.f;
        uint32_t* pw0 = Ps + (wrow + r4) * PS_PAD;
        uint32_t* pw8 = Ps + (wrow + r4 + 8) * PS_PAD;
        #pragma unroll
        for (int nf = 0; nf < 16; nf++) {
            float p0 = __expf(sacc[nf][0] - m0);
            float p1 = __expf(sacc[nf][1] - m0);
            float p2 = __expf(sacc[nf][2] - m8);
            float p3 = __expf(sacc[nf][3] - m8);
            rs0 += p0 + p1; rs8 += p2 + p3;
            int col = nf * 8 + 2 * q4;
            pw0[col] = __float_as_uint(p0); pw0[col + 1] = __float_as_uint(p1);
            pw8[col] = __float_as_uint(p2); pw8[col + 1] = __float_as_uint(p3);
        }
        rs0 += __shfl_xor_sync(0xffffffffu, rs0, 1);
        rs0 += __shfl_xor_sync(0xffffffffu, rs0, 2);
        rs8 += __shfl_xor_sync(0xffffffffu, rs8, 1);
        rs8 += __shfl_xor_sync(0xffffffffu, rs8, 2);
        l0 += rs0; l8 += rs8;
        __syncwarp();

        #pragma unroll
        for (int kk = 0; kk < 16; kk++) {
            uint32_t a0 = Ps[(wrow + r4)     * PS_PAD + kk * 8 + q4];
            uint32_t a1 = Ps[(wrow + r4 + 8) * PS_PAD + kk * 8 + q4];
            uint32_t a2 = Ps[(wrow + r4)     * PS_PAD + kk * 8 + q4 + 4];
            uint32_t a3 = Ps[(wrow + r4 + 8) * PS_PAD + kk * 8 + q4 + 4];
            #pragma unroll
            for (int nf = 0; nf < 8; nf++) {
                uint32_t b0 = Vsl[(kk * 8 + q4)     * VS_PAD + nf * 8 + r4];
                uint32_t b1 = Vsl[(kk * 8 + q4 + 4) * VS_PAD + nf * 8 + r4];
                mma_tf32(oacc[nf], a0, a1, a2, a3, b0, b1);
            }
        }
    }

    const float inv0 = 1.f / l0, inv8 = 1.f / l8;
    const int lg0 = qbase + wrow + r4;
    const int lg8 = lg0 + 8;
    #pragma unroll
    for (int nf = 0; nf < 8; nf++) {
        int d = nf * 8 + 2 * q4;
        int row0 = hh * 128 + (lg0 >> 4), col0 = (lg0 & 15) * 64 + d;
        int row8 = hh * 128 + (lg8 >> 4), col8 = (lg8 & 15) * 64 + d;
        *(float2*)(o_out + ((size_t)(b * SEQL + row0)) * DMODEL + col0) =
            make_float2(oacc[nf][0] * inv0, oacc[nf][1] * inv0);
        *(float2*)(o_out + ((size_t)(b * SEQL + row8)) * DMODEL + col8) =
            make_float2(oacc[nf][2] * inv8, oacc[nf][3] * inv8);
    }
}

// ---------------- residual add + LayerNorm ----------------------------------
__global__ __launch_bounds__(256) void add_ln_kernel(
    const float* __restrict__ a, const float* __restrict__ b,
    const float* __restrict__ g, const float* __restrict__ beta,
    float* __restrict__ out)
{
    const int row = blockIdx.x;
    const int tid = threadIdx.x;
    const float* ar = a + (size_t)row * DMODEL;
    const float* br = b + (size_t)row * DMODEL;

    float x[4];
    float sum = 0.f, sq = 0.f;
    #pragma unroll
    for (int i = 0; i < 4; i++) {
        int c = tid + i * 256;
        x[i] = ar[c] + br[c];
        sum += x[i]; sq += x[i] * x[i];
    }
    #pragma unroll
    for (int off = 16; off; off >>= 1) {
        sum += __shfl_xor_sync(0xffffffffu, sum, off);
        sq  += __shfl_xor_sync(0xffffffffu, sq, off);
    }
    __shared__ float ssum[8], ssq[8];
    const int wid = tid >> 5;
    if ((tid & 31) == 0) { ssum[wid] = sum; ssq[wid] = sq; }
    __syncthreads();
    sum = 0.f; sq = 0.f;
    #pragma unroll
    for (int w = 0; w < 8; w++) { sum += ssum[w]; sq += ssq[w]; }

    const float mean = sum * (1.f / DMODEL);
    const float var  = sq * (1.f / DMODEL) - mean * mean;
    const float rstd = rsqrtf(var + 1e-5f);

    float* orow = out + (size_t)row * DMODEL;
    #pragma unroll
    for (int i = 0; i < 4; i++) {
        int c = tid + i * 256;
        orow[c] = (x[i] - mean) * rstd * g[c] + beta[c];
    }
}

__global__ void concat_bias(const float* a, const float* b, const float* c, float* o)
{
    int i = blockIdx.x * 256 + threadIdx.x;
    if (i < DMODEL) {
        o[i] = a[i]; o[i + DMODEL] = b[i]; o[i + 2 * DMODEL] = c[i];
    }
}

// ---------------- launch ----------------------------------------------------
extern "C" void kernel_launch(void* const* d_in, const int* in_sizes, int n_in,
                              void* d_out, int out_size)
{
    const float* x    = (const float*)d_in[0];
    const float* Wq   = (const float*)d_in[1];
    const float* bq   = (const float*)d_in[2];
    const float* Wk   = (const float*)d_in[3];
    const float* bk   = (const float*)d_in[4];
    const float* Wv   = (const float*)d_in[5];
    const float* bv   = (const float*)d_in[6];
    const float* Wo   = (const float*)d_in[7];
    const float* bo   = (const float*)d_in[8];
    const float* W1   = (const float*)d_in[9];
    const float* b1   = (const float*)d_in[10];
    const float* W2   = (const float*)d_in[11];
    const float* b2   = (const float*)d_in[12];
    const float* g1   = (const float*)d_in[13];
    const float* bt1  = (const float*)d_in[14];
    const float* g2   = (const float*)d_in[15];
    const float* bt2  = (const float*)d_in[16];
    float* out = (float*)d_out;

    float *qkv, *attnv, *tmp, *x1, *ff, *tmp2, *bias3;
    cudaGetSymbolAddress((void**)&qkv,   g_qkv);
    cudaGetSymbolAddress((void**)&attnv, g_attnv);
    cudaGetSymbolAddress((void**)&tmp,   g_tmp);
    cudaGetSymbolAddress((void**)&x1,    g_x1);
    cudaGetSymbolAddress((void**)&ff,    g_ff);
    cudaGetSymbolAddress((void**)&tmp2,  g_tmp2);
    cudaGetSymbolAddress((void**)&bias3, g_bias3);

    cudaFuncSetAttribute(tgemm_bias, cudaFuncAttributeMaxDynamicSharedMemorySize,
                         GEMM_SMEM_BYTES);
    cudaFuncSetAttribute(attn_tc, cudaFuncAttributeMaxDynamicSharedMemorySize,
                         ATT_SMEM_BYTES);

    concat_bias<<<4, 256>>>(bq, bk, bv, bias3);

    // fused QKV projection: [4096 x 1024] @ [1024 x 3072]
    dim3 gQKV(3 * DMODEL / 128, TOKENS / 128);  // (24, 32)
    tgemm_bias<<<gQKV, 256, GEMM_SMEM_BYTES>>>(
        x, Wq, Wk, Wv, bias3, qkv, TOKENS, 3 * DMODEL, DMODEL, DMODEL, 0);

    // tensor-core flash attention (reference's no-transpose reshape epilogue)
    dim3 gA(SEQL / 128, BATCH * NHEADS);        // (16, 32)
    attn_tc<<<gA, 256, ATT_SMEM_BYTES>>>(qkv, attnv);

    // output projection + residual LN
    dim3 gD(DMODEL / 128, TOKENS / 128);        // (8, 32)
    tgemm_bias<<<gD, 256, GEMM_SMEM_BYTES>>>(
        attnv, Wo, nullptr, nullptr, bo, tmp, TOKENS, DMODEL, DMODEL, DMODEL, 0);
    add_ln_kernel<<<TOKENS, 256>>>(tmp, x, g1, bt1, x1);

    // FFN
    dim3 gF(DFF / 128, TOKENS / 128);           // (32, 32)
    tgemm_bias<<<gF, 256, GEMM_SMEM_BYTES>>>(
        x1, W1, nullptr, nullptr, b1, ff, TOKENS, DFF, DMODEL, DFF, 1);
    tgemm_bias<<<gD, 256, GEMM_SMEM_BYTES>>>(
        ff, W2, nullptr, nullptr, b2, tmp2, TOKENS, DMODEL, DFF, DMODEL, 0);
    add_ln_kernel<<<TOKENS, 256>>>(tmp2, x1, g2, bt2, out);
}

// round 13
// speedup vs baseline: 1.7547x; 1.6289x over previous
#include <cuda_runtime.h>
#include <cuda_fp16.h>
#include <math.h>
#include <stdint.h>

#define BATCH 2
#define SEQL  2048
#define DMODEL 1024
#define NHEADS 16
#define DK    64
#define DFF   4096
#define TOKENS (BATCH*SEQL)   // 4096

// ---------------- scratch (device globals: allocation-guard safe) -----------
__device__ __half g_xh[TOKENS*DMODEL];
__device__ __half g_qkvh[TOKENS*3*DMODEL];
__device__ __half g_attnvh[TOKENS*DMODEL];
__device__ __half g_x1h[TOKENS*DMODEL];
__device__ __half g_ffh[TOKENS*DFF];
__device__ float  g_tmp[TOKENS*DMODEL];
__device__ float  g_x1[TOKENS*DMODEL];
__device__ float  g_tmp2[TOKENS*DMODEL];
__device__ float  g_bias3[3*DMODEL];
__device__ __half g_w3h[3*DMODEL*DMODEL];   // [3072][1024]
__device__ __half g_woh[DMODEL*DMODEL];     // [1024][1024]
__device__ __half g_w1h[DFF*DMODEL];        // [4096][1024]
__device__ __half g_w2h[DMODEL*DFF];        // [1024][4096]

// ---------------- helpers ----------------------------------------------------
__device__ __forceinline__ void mma_f16(float c[4],
    uint32_t a0, uint32_t a1, uint32_t a2, uint32_t a3, uint32_t b0, uint32_t b1)
{
    asm volatile(
        "mma.sync.aligned.m16n8k16.row.col.f32.f16.f16.f32 "
        "{%0,%1,%2,%3}, {%4,%5,%6,%7}, {%8,%9}, {%0,%1,%2,%3};"
        : "+f"(c[0]), "+f"(c[1]), "+f"(c[2]), "+f"(c[3])
        : "r"(a0), "r"(a1), "r"(a2), "r"(a3), "r"(b0), "r"(b1));
}
__device__ __forceinline__ void ldsm4(uint32_t& r0, uint32_t& r1,
                                      uint32_t& r2, uint32_t& r3, uint32_t addr)
{
    asm volatile("ldmatrix.sync.aligned.m8n8.x4.shared.b16 {%0,%1,%2,%3}, [%4];"
                 : "=r"(r0), "=r"(r1), "=r"(r2), "=r"(r3) : "r"(addr));
}
__device__ __forceinline__ void ldsm2t(uint32_t& r0, uint32_t& r1, uint32_t addr)
{
    asm volatile("ldmatrix.sync.aligned.m8n8.x2.trans.shared.b16 {%0,%1}, [%2];"
                 : "=r"(r0), "=r"(r1) : "r"(addr));
}
__device__ __forceinline__ void cp16(uint32_t dst, const void* src) {
    asm volatile("cp.async.cg.shared.global [%0], [%1], 16;" :: "r"(dst), "l"(src));
}
__device__ __forceinline__ void cp_commit() { asm volatile("cp.async.commit_group;"); }
__device__ __forceinline__ void cp_wait0()  { asm volatile("cp.async.wait_group 0;"); }
__device__ __forceinline__ void cp_wait1()  { asm volatile("cp.async.wait_group 1;"); }

// ---------------- FP16 GEMM, 128x128 tile, BK=64, 3 stages, 2 CTAs/SM -------
// A:[M][K] fp16, Bt:[N][K] fp16. 8 warps, warp tile 64x32 (4x4 m16n8k16).
// ldmatrix.x4 A-frags, LDS.32-pair B-frags. Epilogue: bias(+GELU), writes
// fp32 C and/or fp16 C16.
#define H_STR 72                       // halves per smem row (64 + 8 pad)
#define ASTGH (128*H_STR)              // halves per A stage
#define STGH  (2*ASTGH)                // halves per stage (A+B)
#define GM_STAGES 3
#define GEMM_SMEM_BYTES (GM_STAGES*STGH*2)   // 108 KB

__global__ __launch_bounds__(256, 2) void hgemm_bias(
    const __half* __restrict__ A, const __half* __restrict__ Bt,
    const float* __restrict__ bias, float* __restrict__ C,
    __half* __restrict__ C16, int N, int K, int gelu)
{
    extern __shared__ __half sh[];
    const uint32_t smB = (uint32_t)__cvta_generic_to_shared(sh);

    const int tid  = threadIdx.x;
    const int lane = tid & 31;
    const int warp = tid >> 5;
    const int r4 = lane >> 2, q4 = lane & 3;
    const int wm = (warp & 1) * 64;
    const int wn = (warp >> 1) * 32;
    const int rowBase = blockIdx.y * 128;
    const int colBase = blockIdx.x * 128;

    const int lmRow = wm + (lane & 15);
    const int lmColB = (lane & 16) ? 16 : 0;   // byte offset (8 halves)

    float acc[4][4][4];
    #pragma unroll
    for (int i = 0; i < 4; i++)
        #pragma unroll
        for (int j = 0; j < 4; j++)
            #pragma unroll
            for (int r = 0; r < 4; r++) acc[i][j][r] = 0.f;

    const int NC = K / 64;

    auto issue_chunk = [&](int j, int s) {
        const uint32_t base = smB + (uint32_t)(s * STGH) * 2u;
        const __half* aSrc = A + (size_t)rowBase * K + j * 64;
        #pragma unroll
        for (int i = 0; i < 4; i++) {
            int f = tid + i * 256;
            int r = f >> 3, c = f & 7;                 // 8 x 16B chunks per row
            cp16(base + (uint32_t)(r * H_STR + c * 8) * 2u,
                 aSrc + (size_t)r * K + c * 8);
        }
        const __half* bSrc = Bt + (size_t)colBase * K + j * 64;
        #pragma unroll
        for (int i = 0; i < 4; i++) {
            int f = tid + i * 256;
            int r = f >> 3, c = f & 7;
            cp16(base + (uint32_t)(ASTGH + r * H_STR + c * 8) * 2u,
                 bSrc + (size_t)r * K + c * 8);
        }
        cp_commit();
    };

    issue_chunk(0, 0);
    issue_chunk(1, 1);

    for (int ic = 0; ic < NC; ic++) {
        if (ic + 1 < NC) cp_wait1(); else cp_wait0();
        __syncthreads();
        if (ic + 2 < NC) issue_chunk(ic + 2, (ic + 2) % GM_STAGES);

        const int s = ic % GM_STAGES;
        const uint32_t aBase = smB + (uint32_t)(s * STGH + lmRow * H_STR) * 2u + lmColB;
        const uint32_t* Bsl = (const uint32_t*)(sh + s * STGH + ASTGH);

        #pragma unroll
        for (int kk = 0; kk < 4; kk++) {             // K = 4 x 16
            uint32_t af[4][4], bf[4][2];
            #pragma unroll
            for (int mf = 0; mf < 4; mf++)
                ldsm4(af[mf][0], af[mf][1], af[mf][2], af[mf][3],
                      aBase + (uint32_t)(mf * 16 * H_STR) * 2u + kk * 32);
            #pragma unroll
            for (int nf = 0; nf < 4; nf++) {
                int nrow = wn + nf * 8 + r4;
                bf[nf][0] = Bsl[nrow * (H_STR/2) + kk * 8 + q4];
                bf[nf][1] = Bsl[nrow * (H_STR/2) + kk * 8 + q4 + 4];
            }
            #pragma unroll
            for (int mf = 0; mf < 4; mf++)
                #pragma unroll
                for (int nf = 0; nf < 4; nf++)
                    mma_f16(acc[mf][nf], af[mf][0], af[mf][1], af[mf][2], af[mf][3],
                            bf[nf][0], bf[nf][1]);
        }
    }

    #pragma unroll
    for (int mf = 0; mf < 4; mf++) {
        #pragma unroll
        for (int nf = 0; nf < 4; nf++) {
            int row = rowBase + wm + mf * 16 + r4;
            int col = colBase + wn + nf * 8 + 2 * q4;
            float v0 = acc[mf][nf][0] + bias[col];
            float v1 = acc[mf][nf][1] + bias[col + 1];
            float v2 = acc[mf][nf][2] + bias[col];
            float v3 = acc[mf][nf][3] + bias[col + 1];
            if (gelu) {
                v0 = 0.5f * v0 * (1.f + erff(v0 * 0.70710678118654752f));
                v1 = 0.5f * v1 * (1.f + erff(v1 * 0.70710678118654752f));
                v2 = 0.5f * v2 * (1.f + erff(v2 * 0.70710678118654752f));
                v3 = 0.5f * v3 * (1.f + erff(v3 * 0.70710678118654752f));
            }
            if (C) {
                *(float2*)(C + (size_t)row * N + col)       = make_float2(v0, v1);
                *(float2*)(C + (size_t)(row + 8) * N + col) = make_float2(v2, v3);
            }
            if (C16) {
                *(__half2*)(C16 + (size_t)row * N + col) =
                    __floats2half2_rn(v0, v1);
                *(__half2*)(C16 + (size_t)(row + 8) * N + col) =
                    __floats2half2_rn(v2, v3);
            }
        }
    }
}

// ---------------- fp16 flash attention ---------------------------------------
// qkv fp16 [4096][3072]; K/V cp.async double-buffered; m16n8k16 MMAs; P via
// smem fp16 (ldmatrix.x4); V b-frags via ldmatrix.x2.trans.
#define AKS 72                          // K/V smem row halves (64+8)
#define KSTGH (128*AKS)
#define PS_STR 136                      // P row halves (128+8)
#define ATT_SMEM_BYTES ((4*KSTGH + 128*PS_STR) * 2)   // ~108.5 KB
#define LDQKV (3*DMODEL)

__global__ __launch_bounds__(256, 1) void attn_h(
    const __half* __restrict__ qkv, __half* __restrict__ o_out)
{
    extern __shared__ __half sh[];
    __half* Ks = sh;                    // [2][128][AKS]
    __half* Vs = sh + 2 * KSTGH;        // [2][128][AKS]
    __half* Ps = sh + 4 * KSTGH;        // [128][PS_STR]
    const uint32_t ksB = (uint32_t)__cvta_generic_to_shared(Ks);
    const uint32_t vsB = (uint32_t)__cvta_generic_to_shared(Vs);
    const uint32_t psB = (uint32_t)__cvta_generic_to_shared(Ps);

    const int tid  = threadIdx.x;
    const int lane = tid & 31;
    const int warp = tid >> 5;
    const int r4 = lane >> 2, q4 = lane & 3;
    const int bh = blockIdx.y;
    const int b  = bh >> 4;
    const int hh = bh & 15;
    const int qbase = blockIdx.x * 128;
    const int wrow  = warp * 16;

    const __half* qp = qkv + ((size_t)(b * SEQL + qbase + wrow)) * LDQKV + hh * DK;
    const __half* kbase = qkv + (size_t)b * SEQL * LDQKV + DMODEL + hh * DK;
    const __half* vbase = qkv + (size_t)b * SEQL * LDQKV + 2 * DMODEL + hh * DK;

    // Q fragments (m16n8k16 A): a0={r4,k,k+1} a1={r4+8} a2={k+8} a3
    uint32_t qf[4][4];
    #pragma unroll
    for (int kk = 0; kk < 4; kk++) {
        qf[kk][0] = *(const uint32_t*)(qp + (size_t)r4       * LDQKV + kk * 16 + 2 * q4);
        qf[kk][1] = *(const uint32_t*)(qp + (size_t)(r4 + 8) * LDQKV + kk * 16 + 2 * q4);
        qf[kk][2] = *(const uint32_t*)(qp + (size_t)r4       * LDQKV + kk * 16 + 2 * q4 + 8);
        qf[kk][3] = *(const uint32_t*)(qp + (size_t)(r4 + 8) * LDQKV + kk * 16 + 2 * q4 + 8);
    }

    float oacc[8][4];
    #pragma unroll
    for (int nf = 0; nf < 8; nf++)
        #pragma unroll
        for (int r = 0; r < 4; r++) oacc[nf][r] = 0.f;

    float m0 = -1e30f, m8 = -1e30f, l0 = 0.f, l8 = 0.f;

    // issue tile 0: 128 keys x 64 halves = 8 x 16B chunks per key
    {
        #pragma unroll
        for (int i = 0; i < 4; i++) {
            int f = tid + i * 256;
            int key = f >> 3, c = f & 7;
            cp16(ksB + (uint32_t)(key * AKS + c * 8) * 2u,
                 kbase + (size_t)key * LDQKV + c * 8);
            cp16(vsB + (uint32_t)(key * AKS + c * 8) * 2u,
                 vbase + (size_t)key * LDQKV + c * 8);
        }
        cp_commit();
    }

    const int NT = SEQL / 128;
    for (int t = 0; t < NT; t++) {
        cp_wait0();
        __syncthreads();

        if (t + 1 < NT) {
            int st = (t + 1) & 1;
            int kt = (t + 1) * 128;
            #pragma unroll
            for (int i = 0; i < 4; i++) {
                int f = tid + i * 256;
                int key = f >> 3, c = f & 7;
                cp16(ksB + (uint32_t)(st * KSTGH + key * AKS + c * 8) * 2u,
                     kbase + (size_t)(kt + key) * LDQKV + c * 8);
                cp16(vsB + (uint32_t)(st * KSTGH + key * AKS + c * 8) * 2u,
                     vbase + (size_t)(kt + key) * LDQKV + c * 8);
            }
            cp_commit();
        }

        const uint32_t* Ksl = (const uint32_t*)(Ks + (t & 1) * KSTGH);
        const uint32_t vtB = vsB + (uint32_t)((t & 1) * KSTGH) * 2u;

        // S = Q @ K^T (16 x 128 per warp), k = 64 (4 x k16)
        float sacc[16][4];
        #pragma unroll
        for (int nf = 0; nf < 16; nf++)
            #pragma unroll
            for (int r = 0; r < 4; r++) sacc[nf][r] = 0.f;

        #pragma unroll
        for (int kk = 0; kk < 4; kk++)
            #pragma unroll
            for (int nf = 0; nf < 16; nf++) {
                int key = nf * 8 + r4;
                uint32_t b0 = Ksl[key * (AKS/2) + kk * 8 + q4];
                uint32_t b1 = Ksl[key * (AKS/2) + kk * 8 + q4 + 4];
                mma_f16(sacc[nf], qf[kk][0], qf[kk][1], qf[kk][2], qf[kk][3], b0, b1);
            }
        #pragma unroll
        for (int nf = 0; nf < 16; nf++) {
            sacc[nf][0] *= 0.125f; sacc[nf][1] *= 0.125f;
            sacc[nf][2] *= 0.125f; sacc[nf][3] *= 0.125f;
        }

        // online softmax (rows r4, r4+8)
        float mx0 = -1e30f, mx8 = -1e30f;
        #pragma unroll
        for (int nf = 0; nf < 16; nf++) {
            mx0 = fmaxf(mx0, fmaxf(sacc[nf][0], sacc[nf][1]));
            mx8 = fmaxf(mx8, fmaxf(sacc[nf][2], sacc[nf][3]));
        }
        mx0 = fmaxf(mx0, __shfl_xor_sync(0xffffffffu, mx0, 1));
        mx0 = fmaxf(mx0, __shfl_xor_sync(0xffffffffu, mx0, 2));
        mx8 = fmaxf(mx8, __shfl_xor_sync(0xffffffffu, mx8, 1));
        mx8 = fmaxf(mx8, __shfl_xor_sync(0xffffffffu, mx8, 2));

        float mn0 = fmaxf(m0, mx0), mn8 = fmaxf(m8, mx8);
        float sc0 = __expf(m0 - mn0), sc8 = __expf(m8 - mn8);
        m0 = mn0; m8 = mn8;
        l0 *= sc0; l8 *= sc8;
        #pragma unroll
        for (int nf = 0; nf < 8; nf++) {
            oacc[nf][0] *= sc0; oacc[nf][1] *= sc0;
            oacc[nf][2] *= sc8; oacc[nf][3] *= sc8;
        }

        float rs0 = 0.f, rs8 = 0.f;
        uint32_t* pw0 = (uint32_t*)Ps + (wrow + r4) * (PS_STR/2);
        uint32_t* pw8 = (uint32_t*)Ps + (wrow + r4 + 8) * (PS_STR/2);
        #pragma unroll
        for (int nf = 0; nf < 16; nf++) {
            float p0 = __expf(sacc[nf][0] - m0);
            float p1 = __expf(sacc[nf][1] - m0);
            float p2 = __expf(sacc[nf][2] - m8);
            float p3 = __expf(sacc[nf][3] - m8);
            rs0 += p0 + p1; rs8 += p2 + p3;
            __half2 h0 = __floats2half2_rn(p0, p1);
            __half2 h8 = __floats2half2_rn(p2, p3);
            pw0[nf * 4 + q4] = *(uint32_t*)&h0;
            pw8[nf * 4 + q4] = *(uint32_t*)&h8;
        }
        rs0 += __shfl_xor_sync(0xffffffffu, rs0, 1);
        rs0 += __shfl_xor_sync(0xffffffffu, rs0, 2);
        rs8 += __shfl_xor_sync(0xffffffffu, rs8, 1);
        rs8 += __shfl_xor_sync(0xffffffffu, rs8, 2);
        l0 += rs0; l8 += rs8;
        __syncwarp();   // P rows are warp-private

        // O += P @ V : k = 128 keys (8 x k16), n = 64 d (8 x n8)
        const uint32_t pBase = psB + (uint32_t)((wrow + (lane & 15)) * PS_STR) * 2u
                               + ((lane & 16) ? 16 : 0);
        #pragma unroll
        for (int kk = 0; kk < 8; kk++) {
            uint32_t a0, a1, a2, a3;
            ldsm4(a0, a1, a2, a3, pBase + kk * 32);
            const uint32_t vRow = vtB + (uint32_t)((kk * 16 + (lane & 15)) * AKS) * 2u;
            #pragma unroll
            for (int nf = 0; nf < 8; nf++) {
                uint32_t b0, b1;
                ldsm2t(b0, b1, vRow + nf * 16);
                mma_f16(oacc[nf], a0, a1, a2, a3, b0, b1);
            }
        }
    }

    // epilogue: reference's no-transpose reshape, fp16 output
    const float inv0 = 1.f / l0, inv8 = 1.f / l8;
    const int lg0 = qbase + wrow + r4;
    const int lg8 = lg0 + 8;
    #pragma unroll
    for (int nf = 0; nf < 8; nf++) {
        int d = nf * 8 + 2 * q4;
        int row0 = hh * 128 + (lg0 >> 4), col0 = (lg0 & 15) * 64 + d;
        int row8 = hh * 128 + (lg8 >> 4), col8 = (lg8 & 15) * 64 + d;
        *(__half2*)(o_out + ((size_t)(b * SEQL + row0)) * DMODEL + col0) =
            __floats2half2_rn(oacc[nf][0] * inv0, oacc[nf][1] * inv0);
        *(__half2*)(o_out + ((size_t)(b * SEQL + row8)) * DMODEL + col8) =
            __floats2half2_rn(oacc[nf][2] * inv8, oacc[nf][3] * inv8);
    }
}

// ---------------- residual add + LayerNorm (fp32 out + optional fp16) -------
__global__ __launch_bounds__(256) void add_ln_kernel(
    const float* __restrict__ a, const float* __restrict__ b,
    const float* __restrict__ g, const float* __restrict__ beta,
    float* __restrict__ out, __half* __restrict__ out16)
{
    const int row = blockIdx.x;
    const int tid = threadIdx.x;
    const float* ar = a + (size_t)row * DMODEL;
    const float* br = b + (size_t)row * DMODEL;

    float x[4];
    float sum = 0.f, sq = 0.f;
    #pragma unroll
    for (int i = 0; i < 4; i++) {
        int c = tid + i * 256;
        x[i] = ar[c] + br[c];
        sum += x[i]; sq += x[i] * x[i];
    }
    #pragma unroll
    for (int off = 16; off; off >>= 1) {
        sum += __shfl_xor_sync(0xffffffffu, sum, off);
        sq  += __shfl_xor_sync(0xffffffffu, sq, off);
    }
    __shared__ float ssum[8], ssq[8];
    const int wid = tid >> 5;
    if ((tid & 31) == 0) { ssum[wid] = sum; ssq[wid] = sq; }
    __syncthreads();
    sum = 0.f; sq = 0.f;
    #pragma unroll
    for (int w = 0; w < 8; w++) { sum += ssum[w]; sq += ssq[w]; }

    const float mean = sum * (1.f / DMODEL);
    const float var  = sq * (1.f / DMODEL) - mean * mean;
    const float rstd = rsqrtf(var + 1e-5f);

    float* orow = out + (size_t)row * DMODEL;
    #pragma unroll
    for (int i = 0; i < 4; i++) {
        int c = tid + i * 256;
        float v = (x[i] - mean) * rstd * g[c] + beta[c];
        orow[c] = v;
        if (out16) out16[(size_t)row * DMODEL + c] = __float2half_rn(v);
    }
}

// ---------------- conversion kernels -----------------------------------------
__global__ __launch_bounds__(256) void cvt_f2h(
    const float* __restrict__ src, __half* __restrict__ dst, int n)
{
    int i = (blockIdx.x * 256 + threadIdx.x) * 4;
    if (i < n) {
        float4 v = *(const float4*)(src + i);
        __half2 h0 = __floats2half2_rn(v.x, v.y);
        __half2 h1 = __floats2half2_rn(v.z, v.w);
        *(__half2*)(dst + i)     = h0;
        *(__half2*)(dst + i + 2) = h1;
    }
}

// src fp32 [K][N] -> dst fp16 [N][K]
__global__ __launch_bounds__(256) void transcvt_w(
    const float* __restrict__ src, __half* __restrict__ dst, int K, int N)
{
    __shared__ float t[32][33];
    const int tx = threadIdx.x & 31, ty = threadIdx.x >> 5;
    const int bx = blockIdx.x * 32, by = blockIdx.y * 32;
    for (int i = ty; i < 32; i += 8)
        t[i][tx] = src[(size_t)(by + i) * N + bx + tx];
    __syncthreads();
    for (int i = ty; i < 32; i += 8)
        dst[(size_t)(bx + i) * K + by + tx] = __float2half_rn(t[tx][i]);
}

__global__ void concat_bias(const float* a, const float* b, const float* c, float* o)
{
    int i = blockIdx.x * 256 + threadIdx.x;
    if (i < DMODEL) {
        o[i] = a[i]; o[i + DMODEL] = b[i]; o[i + 2 * DMODEL] = c[i];
    }
}

// ---------------- launch ----------------------------------------------------
extern "C" void kernel_launch(void* const* d_in, const int* in_sizes, int n_in,
                              void* d_out, int out_size)
{
    const float* x    = (const float*)d_in[0];
    const float* Wq   = (const float*)d_in[1];
    const float* bq   = (const float*)d_in[2];
    const float* Wk   = (const float*)d_in[3];
    const float* bk   = (const float*)d_in[4];
    const float* Wv   = (const float*)d_in[5];
    const float* bv   = (const float*)d_in[6];
    const float* Wo   = (const float*)d_in[7];
    const float* bo   = (const float*)d_in[8];
    const float* W1   = (const float*)d_in[9];
    const float* b1   = (const float*)d_in[10];
    const float* W2   = (const float*)d_in[11];
    const float* b2   = (const float*)d_in[12];
    const float* g1   = (const float*)d_in[13];
    const float* bt1  = (const float*)d_in[14];
    const float* g2   = (const float*)d_in[15];
    const float* bt2  = (const float*)d_in[16];
    float* out = (float*)d_out;

    __half *xh, *qkvh, *attnvh, *x1h, *ffh, *w3h, *woh, *w1h, *w2h;
    float *tmp, *x1, *tmp2, *bias3;
    cudaGetSymbolAddress((void**)&xh,     g_xh);
    cudaGetSymbolAddress((void**)&qkvh,   g_qkvh);
    cudaGetSymbolAddress((void**)&attnvh, g_attnvh);
    cudaGetSymbolAddress((void**)&x1h,    g_x1h);
    cudaGetSymbolAddress((void**)&ffh,    g_ffh);
    cudaGetSymbolAddress((void**)&tmp,    g_tmp);
    cudaGetSymbolAddress((void**)&x1,     g_x1);
    cudaGetSymbolAddress((void**)&tmp2,   g_tmp2);
    cudaGetSymbolAddress((void**)&bias3,  g_bias3);
    cudaGetSymbolAddress((void**)&w3h,    g_w3h);
    cudaGetSymbolAddress((void**)&woh,    g_woh);
    cudaGetSymbolAddress((void**)&w1h,    g_w1h);
    cudaGetSymbolAddress((void**)&w2h,    g_w2h);

    cudaFuncSetAttribute(hgemm_bias, cudaFuncAttributeMaxDynamicSharedMemorySize,
                         GEMM_SMEM_BYTES);
    cudaFuncSetAttribute(attn_h, cudaFuncAttributeMaxDynamicSharedMemorySize,
                         ATT_SMEM_BYTES);

    // conversions: x -> fp16; weights -> fp16 [N][K]
    cvt_f2h<<<(TOKENS*DMODEL/4 + 255)/256, 256>>>(x, xh, TOKENS*DMODEL);
    dim3 tB(256);
    transcvt_w<<<dim3(DMODEL/32, DMODEL/32), tB>>>(Wq, w3h, DMODEL, DMODEL);
    transcvt_w<<<dim3(DMODEL/32, DMODEL/32), tB>>>(Wk, w3h + DMODEL*DMODEL, DMODEL, DMODEL);
    transcvt_w<<<dim3(DMODEL/32, DMODEL/32), tB>>>(Wv, w3h + 2*DMODEL*DMODEL, DMODEL, DMODEL);
    transcvt_w<<<dim3(DMODEL/32, DMODEL/32), tB>>>(Wo, woh, DMODEL, DMODEL);
    transcvt_w<<<dim3(DFF/32,    DMODEL/32), tB>>>(W1, w1h, DMODEL, DFF);
    transcvt_w<<<dim3(DMODEL/32, DFF/32),    tB>>>(W2, w2h, DFF, DMODEL);
    concat_bias<<<4, 256>>>(bq, bk, bv, bias3);

    // fused QKV projection (fp16 out only)
    hgemm_bias<<<dim3(24, 32), 256, GEMM_SMEM_BYTES>>>(
        xh, w3h, bias3, nullptr, qkvh, 3*DMODEL, DMODEL, 0);

    // flash attention (fp16 in/out; reference's no-transpose reshape)
    attn_h<<<dim3(SEQL/128, BATCH*NHEADS), 256, ATT_SMEM_BYTES>>>(qkvh, attnvh);

    // output projection + residual LN (x1 fp32 + fp16)
    hgemm_bias<<<dim3(8, 32), 256, GEMM_SMEM_BYTES>>>(
        attnvh, woh, bo, tmp, nullptr, DMODEL, DMODEL, 0);
    add_ln_kernel<<<TOKENS, 256>>>(tmp, x, g1, bt1, x1, x1h);

    // FFN
    hgemm_bias<<<dim3(32, 32), 256, GEMM_SMEM_BYTES>>>(
        x1h, w1h, b1, nullptr, ffh, DFF, DMODEL, 1);
    hgemm_bias<<<dim3(8, 32), 256, GEMM_SMEM_BYTES>>>(
        ffh, w2h, b2, tmp2, nullptr, DMODEL, DFF, 0);
    add_ln_kernel<<<TOKENS, 256>>>(tmp2, x1, g2, bt2, out, nullptr);
}

// round 14
// speedup vs baseline: 1.7926x; 1.0216x over previous
#include <cuda_runtime.h>
#include <cuda_fp16.h>
#include <math.h>
#include <stdint.h>

#define BATCH 2
#define SEQL  2048
#define DMODEL 1024
#define NHEADS 16
#define DK    64
#define DFF   4096
#define TOKENS (BATCH*SEQL)   // 4096

// ---------------- scratch (device globals: allocation-guard safe) -----------
__device__ __half g_xh[TOKENS*DMODEL];
__device__ __half g_qkvh[TOKENS*3*DMODEL];
__device__ __half g_attnvh[TOKENS*DMODEL];
__device__ __half g_x1h[TOKENS*DMODEL];
__device__ __half g_ffh[TOKENS*DFF];
__device__ float  g_tmp[TOKENS*DMODEL];
__device__ float  g_x1[TOKENS*DMODEL];
__device__ float  g_tmp2[TOKENS*DMODEL];
__device__ float  g_bias3[3*DMODEL];
__device__ __half g_w3h[3*DMODEL*DMODEL];   // [3072][1024]
__device__ __half g_woh[DMODEL*DMODEL];     // [1024][1024]
__device__ __half g_w1h[DFF*DMODEL];        // [4096][1024]
__device__ __half g_w2h[DMODEL*DFF];        // [1024][4096]

// ---------------- helpers ----------------------------------------------------
__device__ __forceinline__ void mma_f16(float c[4],
    uint32_t a0, uint32_t a1, uint32_t a2, uint32_t a3, uint32_t b0, uint32_t b1)
{
    asm volatile(
        "mma.sync.aligned.m16n8k16.row.col.f32.f16.f16.f32 "
        "{%0,%1,%2,%3}, {%4,%5,%6,%7}, {%8,%9}, {%0,%1,%2,%3};"
        : "+f"(c[0]), "+f"(c[1]), "+f"(c[2]), "+f"(c[3])
        : "r"(a0), "r"(a1), "r"(a2), "r"(a3), "r"(b0), "r"(b1));
}
__device__ __forceinline__ void ldsm4(uint32_t& r0, uint32_t& r1,
                                      uint32_t& r2, uint32_t& r3, uint32_t addr)
{
    asm volatile("ldmatrix.sync.aligned.m8n8.x4.shared.b16 {%0,%1,%2,%3}, [%4];"
                 : "=r"(r0), "=r"(r1), "=r"(r2), "=r"(r3) : "r"(addr));
}
__device__ __forceinline__ void ldsm4t(uint32_t& r0, uint32_t& r1,
                                       uint32_t& r2, uint32_t& r3, uint32_t addr)
{
    asm volatile("ldmatrix.sync.aligned.m8n8.x4.trans.shared.b16 {%0,%1,%2,%3}, [%4];"
                 : "=r"(r0), "=r"(r1), "=r"(r2), "=r"(r3) : "r"(addr));
}
__device__ __forceinline__ void cp16(uint32_t dst, const void* src) {
    asm volatile("cp.async.cg.shared.global [%0], [%1], 16;" :: "r"(dst), "l"(src));
}
__device__ __forceinline__ void cp_commit() { asm volatile("cp.async.commit_group;"); }
__device__ __forceinline__ void cp_wait0()  { asm volatile("cp.async.wait_group 0;"); }
__device__ __forceinline__ void cp_wait1()  { asm volatile("cp.async.wait_group 1;"); }

// ---------------- FP16 GEMM, 128x128 tile, BK=64, 3 stages, 2 CTAs/SM -------
// A:[M][K] fp16, Bt:[N][K] fp16. 8 warps, warp tile 64x32 (4x4 m16n8k16).
// ldmatrix.x4 for A-frags AND B-frag pairs (non-trans m8n8 maps exactly to the
// (n, k-pair) B layout). Epilogue: bias(+GELU) -> fp32 C and/or fp16 C16.
#define H_STR 72                       // halves per smem row (64 + 8 pad)
#define ASTGH (128*H_STR)
#define STGH  (2*ASTGH)
#define GM_STAGES 3
#define GEMM_SMEM_BYTES (GM_STAGES*STGH*2)   // 108 KB

__global__ __launch_bounds__(256, 2) void hgemm_bias(
    const __half* __restrict__ A, const __half* __restrict__ Bt,
    const float* __restrict__ bias, float* __restrict__ C,
    __half* __restrict__ C16, int N, int K, int gelu)
{
    extern __shared__ __half sh[];
    const uint32_t smB = (uint32_t)__cvta_generic_to_shared(sh);

    const int tid  = threadIdx.x;
    const int lane = tid & 31;
    const int warp = tid >> 5;
    const int r4 = lane >> 2, q4 = lane & 3;
    const int wm = (warp & 1) * 64;
    const int wn = (warp >> 1) * 32;
    const int rowBase = blockIdx.y * 128;
    const int colBase = blockIdx.x * 128;

    const int lmRow = wm + (lane & 15);
    const int lmColB = (lane & 16) ? 16 : 0;
    // B ldsm lane address (halves): covers nf (lanes<16) and nf+1 (lanes>=16)
    const int bLaneHalf = (wn + (lane & 7) + ((lane >> 4) << 3)) * H_STR
                          + ((lane >> 3) & 1) * 8;

    float acc[4][4][4];
    #pragma unroll
    for (int i = 0; i < 4; i++)
        #pragma unroll
        for (int j = 0; j < 4; j++)
            #pragma unroll
            for (int r = 0; r < 4; r++) acc[i][j][r] = 0.f;

    const int NC = K / 64;

    auto issue_chunk = [&](int j, int s) {
        const uint32_t base = smB + (uint32_t)(s * STGH) * 2u;
        const __half* aSrc = A + (size_t)rowBase * K + j * 64;
        #pragma unroll
        for (int i = 0; i < 4; i++) {
            int f = tid + i * 256;
            int r = f >> 3, c = f & 7;
            cp16(base + (uint32_t)(r * H_STR + c * 8) * 2u,
                 aSrc + (size_t)r * K + c * 8);
        }
        const __half* bSrc = Bt + (size_t)colBase * K + j * 64;
        #pragma unroll
        for (int i = 0; i < 4; i++) {
            int f = tid + i * 256;
            int r = f >> 3, c = f & 7;
            cp16(base + (uint32_t)(ASTGH + r * H_STR + c * 8) * 2u,
                 bSrc + (size_t)r * K + c * 8);
        }
        cp_commit();
    };

    issue_chunk(0, 0);
    issue_chunk(1, 1);

    for (int ic = 0; ic < NC; ic++) {
        if (ic + 1 < NC) cp_wait1(); else cp_wait0();
        __syncthreads();
        if (ic + 2 < NC) issue_chunk(ic + 2, (ic + 2) % GM_STAGES);

        const int s = ic % GM_STAGES;
        const uint32_t aBase = smB + (uint32_t)(s * STGH + lmRow * H_STR) * 2u + lmColB;
        const uint32_t bBase = smB + (uint32_t)(s * STGH + ASTGH + bLaneHalf) * 2u;

        #pragma unroll
        for (int kk = 0; kk < 4; kk++) {
            uint32_t af[4][4], bf[4][2];
            #pragma unroll
            for (int mf = 0; mf < 4; mf++)
                ldsm4(af[mf][0], af[mf][1], af[mf][2], af[mf][3],
                      aBase + (uint32_t)(mf * 16 * H_STR) * 2u + kk * 32);
            #pragma unroll
            for (int nf = 0; nf < 4; nf += 2)
                ldsm4(bf[nf][0], bf[nf][1], bf[nf+1][0], bf[nf+1][1],
                      bBase + (uint32_t)(nf * 8 * H_STR) * 2u + kk * 32);
            #pragma unroll
            for (int mf = 0; mf < 4; mf++)
                #pragma unroll
                for (int nf = 0; nf < 4; nf++)
                    mma_f16(acc[mf][nf], af[mf][0], af[mf][1], af[mf][2], af[mf][3],
                            bf[nf][0], bf[nf][1]);
        }
    }

    #pragma unroll
    for (int mf = 0; mf < 4; mf++) {
        #pragma unroll
        for (int nf = 0; nf < 4; nf++) {
            int row = rowBase + wm + mf * 16 + r4;
            int col = colBase + wn + nf * 8 + 2 * q4;
            float v0 = acc[mf][nf][0] + bias[col];
            float v1 = acc[mf][nf][1] + bias[col + 1];
            float v2 = acc[mf][nf][2] + bias[col];
            float v3 = acc[mf][nf][3] + bias[col + 1];
            if (gelu) {
                v0 = 0.5f * v0 * (1.f + erff(v0 * 0.70710678118654752f));
                v1 = 0.5f * v1 * (1.f + erff(v1 * 0.70710678118654752f));
                v2 = 0.5f * v2 * (1.f + erff(v2 * 0.70710678118654752f));
                v3 = 0.5f * v3 * (1.f + erff(v3 * 0.70710678118654752f));
            }
            if (C) {
                *(float2*)(C + (size_t)row * N + col)       = make_float2(v0, v1);
                *(float2*)(C + (size_t)(row + 8) * N + col) = make_float2(v2, v3);
            }
            if (C16) {
                *(__half2*)(C16 + (size_t)row * N + col) =
                    __floats2half2_rn(v0, v1);
                *(__half2*)(C16 + (size_t)(row + 8) * N + col) =
                    __floats2half2_rn(v2, v3);
            }
        }
    }
}

// ---------------- fp16 flash attention ---------------------------------------
#define AKS 72
#define KSTGH (128*AKS)
#define PS_STR 136
#define ATT_SMEM_BYTES ((4*KSTGH + 128*PS_STR) * 2)   // ~108.5 KB
#define LDQKV (3*DMODEL)

__global__ __launch_bounds__(256, 1) void attn_h(
    const __half* __restrict__ qkv, __half* __restrict__ o_out)
{
    extern __shared__ __half sh[];
    __half* Ks = sh;
    __half* Vs = sh + 2 * KSTGH;
    __half* Ps = sh + 4 * KSTGH;
    const uint32_t ksB = (uint32_t)__cvta_generic_to_shared(Ks);
    const uint32_t vsB = (uint32_t)__cvta_generic_to_shared(Vs);
    const uint32_t psB = (uint32_t)__cvta_generic_to_shared(Ps);

    const int tid  = threadIdx.x;
    const int lane = tid & 31;
    const int warp = tid >> 5;
    const int r4 = lane >> 2, q4 = lane & 3;
    const int bh = blockIdx.y;
    const int b  = bh >> 4;
    const int hh = bh & 15;
    const int qbase = blockIdx.x * 128;
    const int wrow  = warp * 16;

    const __half* qp = qkv + ((size_t)(b * SEQL + qbase + wrow)) * LDQKV + hh * DK;
    const __half* kbase = qkv + (size_t)b * SEQL * LDQKV + DMODEL + hh * DK;
    const __half* vbase = qkv + (size_t)b * SEQL * LDQKV + 2 * DMODEL + hh * DK;

    uint32_t qf[4][4];
    #pragma unroll
    for (int kk = 0; kk < 4; kk++) {
        qf[kk][0] = *(const uint32_t*)(qp + (size_t)r4       * LDQKV + kk * 16 + 2 * q4);
        qf[kk][1] = *(const uint32_t*)(qp + (size_t)(r4 + 8) * LDQKV + kk * 16 + 2 * q4);
        qf[kk][2] = *(const uint32_t*)(qp + (size_t)r4       * LDQKV + kk * 16 + 2 * q4 + 8);
        qf[kk][3] = *(const uint32_t*)(qp + (size_t)(r4 + 8) * LDQKV + kk * 16 + 2 * q4 + 8);
    }

    // ldsm lane addresses (halves / bytes)
    const int kLaneHalf = ((lane & 7) + ((lane >> 4) << 3)) * AKS
                          + ((lane >> 3) & 1) * 8;
    const int vLaneByte = (lane & 15) * AKS * 2 + (lane >> 4) * 16;

    float oacc[8][4];
    #pragma unroll
    for (int nf = 0; nf < 8; nf++)
        #pragma unroll
        for (int r = 0; r < 4; r++) oacc[nf][r] = 0.f;

    float m0 = -1e30f, m8 = -1e30f, l0 = 0.f, l8 = 0.f;

    {
        #pragma unroll
        for (int i = 0; i < 4; i++) {
            int f = tid + i * 256;
            int key = f >> 3, c = f & 7;
            cp16(ksB + (uint32_t)(key * AKS + c * 8) * 2u,
                 kbase + (size_t)key * LDQKV + c * 8);
            cp16(vsB + (uint32_t)(key * AKS + c * 8) * 2u,
                 vbase + (size_t)key * LDQKV + c * 8);
        }
        cp_commit();
    }

    const int NT = SEQL / 128;
    for (int t = 0; t < NT; t++) {
        cp_wait0();
        __syncthreads();

        if (t + 1 < NT) {
            int st = (t + 1) & 1;
            int kt = (t + 1) * 128;
            #pragma unroll
            for (int i = 0; i < 4; i++) {
                int f = tid + i * 256;
                int key = f >> 3, c = f & 7;
                cp16(ksB + (uint32_t)(st * KSTGH + key * AKS + c * 8) * 2u,
                     kbase + (size_t)(kt + key) * LDQKV + c * 8);
                cp16(vsB + (uint32_t)(st * KSTGH + key * AKS + c * 8) * 2u,
                     vbase + (size_t)(kt + key) * LDQKV + c * 8);
            }
            cp_commit();
        }

        const uint32_t kTile = ksB + (uint32_t)((t & 1) * KSTGH + kLaneHalf) * 2u;
        const uint32_t vTile = vsB + (uint32_t)((t & 1) * KSTGH) * 2u;

        // S = Q @ K^T (16 x 128 per warp), K-frags via ldsm4 pairs
        float sacc[16][4];
        #pragma unroll
        for (int nf = 0; nf < 16; nf++)
            #pragma unroll
            for (int r = 0; r < 4; r++) sacc[nf][r] = 0.f;

        #pragma unroll
        for (int kk = 0; kk < 4; kk++)
            #pragma unroll
            for (int nf = 0; nf < 16; nf += 2) {
                uint32_t b0, b1, b2, b3;
                ldsm4(b0, b1, b2, b3,
                      kTile + (uint32_t)(nf * 8 * AKS) * 2u + kk * 32);
                mma_f16(sacc[nf],     qf[kk][0], qf[kk][1], qf[kk][2], qf[kk][3], b0, b1);
                mma_f16(sacc[nf + 1], qf[kk][0], qf[kk][1], qf[kk][2], qf[kk][3], b2, b3);
            }
        #pragma unroll
        for (int nf = 0; nf < 16; nf++) {
            sacc[nf][0] *= 0.125f; sacc[nf][1] *= 0.125f;
            sacc[nf][2] *= 0.125f; sacc[nf][3] *= 0.125f;
        }

        float mx0 = -1e30f, mx8 = -1e30f;
        #pragma unroll
        for (int nf = 0; nf < 16; nf++) {
            mx0 = fmaxf(mx0, fmaxf(sacc[nf][0], sacc[nf][1]));
            mx8 = fmaxf(mx8, fmaxf(sacc[nf][2], sacc[nf][3]));
        }
        mx0 = fmaxf(mx0, __shfl_xor_sync(0xffffffffu, mx0, 1));
        mx0 = fmaxf(mx0, __shfl_xor_sync(0xffffffffu, mx0, 2));
        mx8 = fmaxf(mx8, __shfl_xor_sync(0xffffffffu, mx8, 1));
        mx8 = fmaxf(mx8, __shfl_xor_sync(0xffffffffu, mx8, 2));

        float mn0 = fmaxf(m0, mx0), mn8 = fmaxf(m8, mx8);
        float sc0 = __expf(m0 - mn0), sc8 = __expf(m8 - mn8);
        m0 = mn0; m8 = mn8;
        l0 *= sc0; l8 *= sc8;
        #pragma unroll
        for (int nf = 0; nf < 8; nf++) {
            oacc[nf][0] *= sc0; oacc[nf][1] *= sc0;
            oacc[nf][2] *= sc8; oacc[nf][3] *= sc8;
        }

        float rs0 = 0.f, rs8 = 0.f;
        uint32_t* pw0 = (uint32_t*)Ps + (wrow + r4) * (PS_STR/2);
        uint32_t* pw8 = (uint32_t*)Ps + (wrow + r4 + 8) * (PS_STR/2);
        #pragma unroll
        for (int nf = 0; nf < 16; nf++) {
            float p0 = __expf(sacc[nf][0] - m0);
            float p1 = __expf(sacc[nf][1] - m0);
            float p2 = __expf(sacc[nf][2] - m8);
            float p3 = __expf(sacc[nf][3] - m8);
            rs0 += p0 + p1; rs8 += p2 + p3;
            __half2 h0 = __floats2half2_rn(p0, p1);
            __half2 h8 = __floats2half2_rn(p2, p3);
            pw0[nf * 4 + q4] = *(uint32_t*)&h0;
            pw8[nf * 4 + q4] = *(uint32_t*)&h8;
        }
        rs0 += __shfl_xor_sync(0xffffffffu, rs0, 1);
        rs0 += __shfl_xor_sync(0xffffffffu, rs0, 2);
        rs8 += __shfl_xor_sync(0xffffffffu, rs8, 1);
        rs8 += __shfl_xor_sync(0xffffffffu, rs8, 2);
        l0 += rs0; l8 += rs8;
        __syncwarp();

        // O += P @ V; V-frags via ldsm4.trans pairs
        const uint32_t pBase = psB + (uint32_t)((wrow + (lane & 15)) * PS_STR) * 2u
                               + ((lane & 16) ? 16 : 0);
        #pragma unroll
        for (int kk = 0; kk < 8; kk++) {
            uint32_t a0, a1, a2, a3;
            ldsm4(a0, a1, a2, a3, pBase + kk * 32);
            const uint32_t vRow = vTile + (uint32_t)(kk * 16 * AKS) * 2u + vLaneByte;
            #pragma unroll
            for (int nf = 0; nf < 8; nf += 2) {
                uint32_t v0, v1, v2, v3;
                ldsm4t(v0, v1, v2, v3, vRow + nf * 16);
                mma_f16(oacc[nf],     a0, a1, a2, a3, v0, v1);
                mma_f16(oacc[nf + 1], a0, a1, a2, a3, v2, v3);
            }
        }
    }

    const float inv0 = 1.f / l0, inv8 = 1.f / l8;
    const int lg0 = qbase + wrow + r4;
    const int lg8 = lg0 + 8;
    #pragma unroll
    for (int nf = 0; nf < 8; nf++) {
        int d = nf * 8 + 2 * q4;
        int row0 = hh * 128 + (lg0 >> 4), col0 = (lg0 & 15) * 64 + d;
        int row8 = hh * 128 + (lg8 >> 4), col8 = (lg8 & 15) * 64 + d;
        *(__half2*)(o_out + ((size_t)(b * SEQL + row0)) * DMODEL + col0) =
            __floats2half2_rn(oacc[nf][0] * inv0, oacc[nf][1] * inv0);
        *(__half2*)(o_out + ((size_t)(b * SEQL + row8)) * DMODEL + col8) =
            __floats2half2_rn(oacc[nf][2] * inv8, oacc[nf][3] * inv8);
    }
}

// ---------------- residual add + LayerNorm (fp32 out + optional fp16) -------
__global__ __launch_bounds__(256) void add_ln_kernel(
    const float* __restrict__ a, const float* __restrict__ b,
    const float* __restrict__ g, const float* __restrict__ beta,
    float* __restrict__ out, __half* __restrict__ out16)
{
    const int row = blockIdx.x;
    const int tid = threadIdx.x;
    const float* ar = a + (size_t)row * DMODEL;
    const float* br = b + (size_t)row * DMODEL;

    float x[4];
    float sum = 0.f, sq = 0.f;
    #pragma unroll
    for (int i = 0; i < 4; i++) {
        int c = tid + i * 256;
        x[i] = ar[c] + br[c];
        sum += x[i]; sq += x[i] * x[i];
    }
    #pragma unroll
    for (int off = 16; off; off >>= 1) {
        sum += __shfl_xor_sync(0xffffffffu, sum, off);
        sq  += __shfl_xor_sync(0xffffffffu, sq, off);
    }
    __shared__ float ssum[8], ssq[8];
    const int wid = tid >> 5;
    if ((tid & 31) == 0) { ssum[wid] = sum; ssq[wid] = sq; }
    __syncthreads();
    sum = 0.f; sq = 0.f;
    #pragma unroll
    for (int w = 0; w < 8; w++) { sum += ssum[w]; sq += ssq[w]; }

    const float mean = sum * (1.f / DMODEL);
    const float var  = sq * (1.f / DMODEL) - mean * mean;
    const float rstd = rsqrtf(var + 1e-5f);

    float* orow = out + (size_t)row * DMODEL;
    #pragma unroll
    for (int i = 0; i < 4; i++) {
        int c = tid + i * 256;
        float v = (x[i] - mean) * rstd * g[c] + beta[c];
        orow[c] = v;
        if (out16) out16[(size_t)row * DMODEL + c] = __float2half_rn(v);
    }
}

// ---------------- conversion kernels -----------------------------------------
__global__ __launch_bounds__(256) void cvt_f2h(
    const float* __restrict__ src, __half* __restrict__ dst, int n)
{
    int i = (blockIdx.x * 256 + threadIdx.x) * 4;
    if (i < n) {
        float4 v = *(const float4*)(src + i);
        *(__half2*)(dst + i)     = __floats2half2_rn(v.x, v.y);
        *(__half2*)(dst + i + 2) = __floats2half2_rn(v.z, v.w);
    }
}

// src fp32 [K][N] -> dst fp16 [N][K]
__global__ __launch_bounds__(256) void transcvt_w(
    const float* __restrict__ src, __half* __restrict__ dst, int K, int N)
{
    __shared__ float t[32][33];
    const int tx = threadIdx.x & 31, ty = threadIdx.x >> 5;
    const int bx = blockIdx.x * 32, by = blockIdx.y * 32;
    for (int i = ty; i < 32; i += 8)
        t[i][tx] = src[(size_t)(by + i) * N + bx + tx];
    __syncthreads();
    for (int i = ty; i < 32; i += 8)
        dst[(size_t)(bx + i) * K + by + tx] = __float2half_rn(t[tx][i]);
}

// batched QKV transpose: z selects Wq/Wk/Wv -> w3h + z*DMODEL*DMODEL
__global__ __launch_bounds__(256) void transcvt_qkv(
    const float* __restrict__ Wq, const float* __restrict__ Wk,
    const float* __restrict__ Wv, __half* __restrict__ dst)
{
    __shared__ float t[32][33];
    const float* src = (blockIdx.z == 0) ? Wq : (blockIdx.z == 1) ? Wk : Wv;
    __half* d = dst + (size_t)blockIdx.z * DMODEL * DMODEL;
    const int tx = threadIdx.x & 31, ty = threadIdx.x >> 5;
    const int bx = blockIdx.x * 32, by = blockIdx.y * 32;
    for (int i = ty; i < 32; i += 8)
        t[i][tx] = src[(size_t)(by + i) * DMODEL + bx + tx];
    __syncthreads();
    for (int i = ty; i < 32; i += 8)
        d[(size_t)(bx + i) * DMODEL + by + tx] = __float2half_rn(t[tx][i]);
}

__global__ void concat_bias(const float* a, const float* b, const float* c, float* o)
{
    int i = blockIdx.x * 256 + threadIdx.x;
    if (i < DMODEL) {
        o[i] = a[i]; o[i + DMODEL] = b[i]; o[i + 2 * DMODEL] = c[i];
    }
}

// ---------------- launch ----------------------------------------------------
extern "C" void kernel_launch(void* const* d_in, const int* in_sizes, int n_in,
                              void* d_out, int out_size)
{
    const float* x    = (const float*)d_in[0];
    const float* Wq   = (const float*)d_in[1];
    const float* bq   = (const float*)d_in[2];
    const float* Wk   = (const float*)d_in[3];
    const float* bk   = (const float*)d_in[4];
    const float* Wv   = (const float*)d_in[5];
    const float* bv   = (const float*)d_in[6];
    const float* Wo   = (const float*)d_in[7];
    const float* bo   = (const float*)d_in[8];
    const float* W1   = (const float*)d_in[9];
    const float* b1   = (const float*)d_in[10];
    const float* W2   = (const float*)d_in[11];
    const float* b2   = (const float*)d_in[12];
    const float* g1   = (const float*)d_in[13];
    const float* bt1  = (const float*)d_in[14];
    const float* g2   = (const float*)d_in[15];
    const float* bt2  = (const float*)d_in[16];
    float* out = (float*)d_out;

    __half *xh, *qkvh, *attnvh, *x1h, *ffh, *w3h, *woh, *w1h, *w2h;
    float *tmp, *x1, *tmp2, *bias3;
    cudaGetSymbolAddress((void**)&xh,     g_xh);
    cudaGetSymbolAddress((void**)&qkvh,   g_qkvh);
    cudaGetSymbolAddress((void**)&attnvh, g_attnvh);
    cudaGetSymbolAddress((void**)&x1h,    g_x1h);
    cudaGetSymbolAddress((void**)&ffh,    g_ffh);
    cudaGetSymbolAddress((void**)&tmp,    g_tmp);
    cudaGetSymbolAddress((void**)&x1,     g_x1);
    cudaGetSymbolAddress((void**)&tmp2,   g_tmp2);
    cudaGetSymbolAddress((void**)&bias3,  g_bias3);
    cudaGetSymbolAddress((void**)&w3h,    g_w3h);
    cudaGetSymbolAddress((void**)&woh,    g_woh);
    cudaGetSymbolAddress((void**)&w1h,    g_w1h);
    cudaGetSymbolAddress((void**)&w2h,    g_w2h);

    cudaFuncSetAttribute(hgemm_bias, cudaFuncAttributeMaxDynamicSharedMemorySize,
                         GEMM_SMEM_BYTES);
    cudaFuncSetAttribute(attn_h, cudaFuncAttributeMaxDynamicSharedMemorySize,
                         ATT_SMEM_BYTES);

    // conversions
    cvt_f2h<<<(TOKENS*DMODEL/4 + 255)/256, 256>>>(x, xh, TOKENS*DMODEL);
    dim3 tB(256);
    transcvt_qkv<<<dim3(DMODEL/32, DMODEL/32, 3), tB>>>(Wq, Wk, Wv, w3h);
    transcvt_w<<<dim3(DMODEL/32, DMODEL/32), tB>>>(Wo, woh, DMODEL, DMODEL);
    transcvt_w<<<dim3(DFF/32,    DMODEL/32), tB>>>(W1, w1h, DMODEL, DFF);
    transcvt_w<<<dim3(DMODEL/32, DFF/32),    tB>>>(W2, w2h, DFF, DMODEL);
    concat_bias<<<4, 256>>>(bq, bk, bv, bias3);

    // fused QKV projection (fp16 out)
    hgemm_bias<<<dim3(24, 32), 256, GEMM_SMEM_BYTES>>>(
        xh, w3h, bias3, nullptr, qkvh, 3*DMODEL, DMODEL, 0);

    // flash attention (fp16; reference's no-transpose reshape epilogue)
    attn_h<<<dim3(SEQL/128, BATCH*NHEADS), 256, ATT_SMEM_BYTES>>>(qkvh, attnvh);

    // output projection + residual LN
    hgemm_bias<<<dim3(8, 32), 256, GEMM_SMEM_BYTES>>>(
        attnvh, woh, bo, tmp, nullptr, DMODEL, DMODEL, 0);
    add_ln_kernel<<<TOKENS, 256>>>(tmp, x, g1, bt1, x1, x1h);

    // FFN
    hgemm_bias<<<dim3(32, 32), 256, GEMM_SMEM_BYTES>>>(
        x1h, w1h, b1, nullptr, ffh, DFF, DMODEL, 1);
    hgemm_bias<<<dim3(8, 32), 256, GEMM_SMEM_BYTES>>>(
        ffh, w2h, b2, tmp2, nullptr, DMODEL, DFF, 0);
    add_ln_kernel<<<TOKENS, 256>>>(tmp2, x1, g2, bt2, out, nullptr);
}